// round 10
// baseline (speedup 1.0000x reference)
#include <cuda_runtime.h>
#include <cuda_bf16.h>
#include <cstdint>

// Problem constants
static constexpr int B   = 8;
static constexpr int T   = 1024;
static constexpr int S   = 1024;
static constexpr int H   = 16;
static constexpr int D   = 64;
static constexpr int EMB = 1024;
static constexpr int QIN = 1024;
static constexpr int KVIN = 256;
static constexpr float SCALING = 0.125f;
static constexpr float LOG2E = 1.4426950408889634f;

// ---------------------------------------------------------------------------
// Scratch (__device__ globals; allocation-free rule)
// ---------------------------------------------------------------------------
__device__ __nv_bfloat16 g_HShi[B * T * QIN],  g_HSlo[B * T * QIN];      // split hs
__device__ __nv_bfloat16 g_KVhi[B * S * KVIN], g_KVlo[B * S * KVIN];     // split kv

__device__ __nv_bfloat16 g_Qhi[B * T * EMB], g_Qlo[B * T * EMB];
__device__ __nv_bfloat16 g_Khi[B * S * EMB], g_Klo[B * S * EMB];
__device__ __nv_bfloat16 g_Vhi[B * S * EMB], g_Vlo[B * S * EMB];
__device__ __nv_bfloat16 g_Vthi[B * H * D * S], g_Vtlo[B * H * D * S];   // [z*D+d][S]
__device__ __nv_bfloat16 g_Chi[B * T * EMB], g_Clo[B * T * EMB];         // ctx

__device__ __nv_bfloat16 g_Wqthi[EMB * QIN],  g_Wqtlo[EMB * QIN];        // [N][K]
__device__ __nv_bfloat16 g_Wkthi[EMB * KVIN], g_Wktlo[EMB * KVIN];
__device__ __nv_bfloat16 g_Wvthi[EMB * KVIN], g_Wvtlo[EMB * KVIN];
__device__ __nv_bfloat16 g_Wothi[EMB * EMB],  g_Wotlo[EMB * EMB];

// ---------------------------------------------------------------------------
// Low-level helpers
// ---------------------------------------------------------------------------
static constexpr int LDSS = 40;   // smem row stride (bf16) for 32-col proj tiles

__device__ __forceinline__ uint32_t ld32(const __nv_bfloat16* p) {
    return *reinterpret_cast<const uint32_t*>(p);
}
__device__ __forceinline__ uint32_t s2u(const void* p) {
    return (uint32_t)__cvta_generic_to_shared(p);
}
__device__ __forceinline__ void cpa16(uint32_t dst, const void* src) {
    asm volatile("cp.async.cg.shared.global [%0], [%1], 16;\n" :: "r"(dst), "l"(src));
}
__device__ __forceinline__ void cpcommit() {
    asm volatile("cp.async.commit_group;\n");
}
template <int N> __device__ __forceinline__ void cpwait() {
    asm volatile("cp.async.wait_group %0;\n" :: "n"(N));
}
__device__ __forceinline__ void ldsm4(uint32_t* r, uint32_t a) {
    asm volatile("ldmatrix.sync.aligned.m8n8.x4.shared.b16 {%0,%1,%2,%3}, [%4];\n"
                 : "=r"(r[0]), "=r"(r[1]), "=r"(r[2]), "=r"(r[3]) : "r"(a));
}
__device__ __forceinline__ void mma16816(float* c, const uint32_t* a, const uint32_t* b) {
    asm volatile(
        "mma.sync.aligned.m16n8k16.row.col.f32.bf16.bf16.f32 "
        "{%0,%1,%2,%3}, {%4,%5,%6,%7}, {%8,%9}, {%0,%1,%2,%3};\n"
        : "+f"(c[0]), "+f"(c[1]), "+f"(c[2]), "+f"(c[3])
        : "r"(a[0]), "r"(a[1]), "r"(a[2]), "r"(a[3]), "r"(b[0]), "r"(b[1]));
}
__device__ __forceinline__ float ex2(float x) {
    float y;
    asm("ex2.approx.f32 %0, %1;" : "=f"(y) : "f"(x));
    return y;
}
__device__ __forceinline__ void split2(float v0, float v1, uint32_t& hi, uint32_t& lo) {
    __nv_bfloat16 h0 = __float2bfloat16(v0), h1 = __float2bfloat16(v1);
    __nv_bfloat16 l0 = __float2bfloat16(v0 - __bfloat162float(h0));
    __nv_bfloat16 l1 = __float2bfloat16(v1 - __bfloat162float(h1));
    __nv_bfloat162 hp; hp.x = h0; hp.y = h1;
    __nv_bfloat162 lp; lp.x = l0; lp.y = l1;
    hi = *reinterpret_cast<uint32_t*>(&hp);
    lo = *reinterpret_cast<uint32_t*>(&lp);
}

// ---------------------------------------------------------------------------
// Activation split: fp32 -> bf16 hi/lo (elementwise, vectorized)
// ---------------------------------------------------------------------------
__global__ __launch_bounds__(256)
void split_act(const float* __restrict__ x,
               __nv_bfloat16* __restrict__ xh, __nv_bfloat16* __restrict__ xl, int n4)
{
    int i = blockIdx.x * 256 + threadIdx.x;
    if (i >= n4) return;
    float4 v = reinterpret_cast<const float4*>(x)[i];
    float vv[4] = {v.x, v.y, v.z, v.w};
    __align__(8) __nv_bfloat16 h[4], l[4];
    #pragma unroll
    for (int j = 0; j < 4; j++) {
        h[j] = __float2bfloat16(vv[j]);
        l[j] = __float2bfloat16(vv[j] - __bfloat162float(h[j]));
    }
    reinterpret_cast<uint2*>(xh)[i] = *reinterpret_cast<uint2*>(h);
    reinterpret_cast<uint2*>(xl)[i] = *reinterpret_cast<uint2*>(l);
}

// ---------------------------------------------------------------------------
// Weight transpose + split: W [K,N] fp32 -> Wt_hi/lo [N,K] bf16
// ---------------------------------------------------------------------------
__global__ __launch_bounds__(256)
void wsplit_t(const float* __restrict__ W, int K, int N,
              __nv_bfloat16* __restrict__ Whi, __nv_bfloat16* __restrict__ Wlo)
{
    __shared__ float sm[32][33];
    const int k0 = blockIdx.y * 32, n0 = blockIdx.x * 32;
    const int tid = threadIdx.x;

    for (int i = tid; i < 32 * 8; i += 256) {
        int r = i >> 3, c4 = i & 7;
        float4 v = *reinterpret_cast<const float4*>(&W[(size_t)(k0 + r) * N + n0 + c4 * 4]);
        sm[r][c4 * 4 + 0] = v.x; sm[r][c4 * 4 + 1] = v.y;
        sm[r][c4 * 4 + 2] = v.z; sm[r][c4 * 4 + 3] = v.w;
    }
    __syncthreads();
    for (int i = tid; i < 32 * 8; i += 256) {
        int n = i >> 3, k4 = i & 7;
        __align__(8) __nv_bfloat16 h[4], l[4];
        #pragma unroll
        for (int j = 0; j < 4; j++) {
            float v = sm[k4 * 4 + j][n];
            h[j] = __float2bfloat16(v);
            l[j] = __float2bfloat16(v - __bfloat162float(h[j]));
        }
        *reinterpret_cast<uint2*>(&Whi[(size_t)(n0 + n) * K + k0 + k4 * 4]) = *reinterpret_cast<uint2*>(h);
        *reinterpret_cast<uint2*>(&Wlo[(size_t)(n0 + n) * K + k0 + k4 * 4]) = *reinterpret_cast<uint2*>(l);
    }
}

// ---------------------------------------------------------------------------
// V transpose (bf16): V [b*S+s][h*D+d] -> Vt [(b*H+h)*D+d][s]
// ---------------------------------------------------------------------------
__global__ __launch_bounds__(256)
void vtrans(const __nv_bfloat16* __restrict__ Vh, const __nv_bfloat16* __restrict__ Vl,
            __nv_bfloat16* __restrict__ Vth, __nv_bfloat16* __restrict__ Vtl)
{
    __shared__ __nv_bfloat16 sm[64][72];
    const int z = blockIdx.z, bb = z >> 4, hh = z & 15;
    const int s0 = blockIdx.x * 64;

    #pragma unroll
    for (int p = 0; p < 2; p++) {
        const __nv_bfloat16* src = p ? Vl : Vh;
        __nv_bfloat16* dst = p ? Vtl : Vth;
        const __nv_bfloat16* sp = src + (size_t)(bb * S + s0) * EMB + hh * D;
        for (int i = threadIdx.x; i < 64 * 16; i += 256) {
            int s = i >> 4, d4 = i & 15;
            *reinterpret_cast<uint2*>(&sm[s][d4 * 4]) =
                *reinterpret_cast<const uint2*>(&sp[(size_t)s * EMB + d4 * 4]);
        }
        __syncthreads();
        __nv_bfloat16* dp = dst + (size_t)z * D * S + s0;
        for (int i = threadIdx.x; i < 64 * 16; i += 256) {
            int d = i >> 4, s4 = i & 15;
            __align__(8) __nv_bfloat16 t[4];
            t[0] = sm[s4 * 4 + 0][d]; t[1] = sm[s4 * 4 + 1][d];
            t[2] = sm[s4 * 4 + 2][d]; t[3] = sm[s4 * 4 + 3][d];
            *reinterpret_cast<uint2*>(&dp[(size_t)d * S + s4 * 4]) = *reinterpret_cast<uint2*>(t);
        }
        __syncthreads();
    }
}

// ---------------------------------------------------------------------------
// Projection GEMM (NT), split-bf16 3-MMA, 3-stage cp.async pipeline + ldmatrix.
// C[M,N] = (A[M,K] @ Bt[N,K]^T + bias) * alpha
// BM=BN=128, BK=32, 256 threads (8 warps 2x4), warp tile 64x32.
// ONE __syncthreads per iteration (3-stage: overwritten buffer last read 2 iters ago).
// ---------------------------------------------------------------------------
static constexpr int PTILE = 128 * LDSS;
static constexpr int PROJ_SMEM = 3 * 4 * PTILE * (int)sizeof(__nv_bfloat16);  // 122880

template <bool OUT_SPLIT>
__global__ __launch_bounds__(256)
void proj_nt(int K,
             const __nv_bfloat16* __restrict__ Ah, const __nv_bfloat16* __restrict__ Al,
             int lda,
             const __nv_bfloat16* __restrict__ Bth, const __nv_bfloat16* __restrict__ Btl,
             float* __restrict__ Cf,
             __nv_bfloat16* __restrict__ Ch, __nv_bfloat16* __restrict__ Cl,
             int ldc, const float* __restrict__ bias, float alpha)
{
    extern __shared__ __nv_bfloat16 smp[];   // [3][4][PTILE]

    const int tid = threadIdx.x, lane = tid & 31, wid = tid >> 5;
    const int wm = wid >> 2, wn = wid & 3;
    const int row0 = blockIdx.y * 128, col0 = blockIdx.x * 128;

    const __nv_bfloat16* aH = Ah + (size_t)row0 * lda;
    const __nv_bfloat16* aL = Al + (size_t)row0 * lda;
    const __nv_bfloat16* bH = Bth + (size_t)col0 * K;
    const __nv_bfloat16* bL = Btl + (size_t)col0 * K;

    const int g = lane >> 3, li = lane & 7;
    const int ar = ((g & 1) * 8) + li, ac = (g >> 1) * 8;   // A-frag ldmatrix lane map
    const int br = ((g >> 1) * 8) + li, bc = (g & 1) * 8;   // B-frag ldmatrix lane map

    float acc[4][4][4] = {};

    auto stage = [&](int st, int k0) {
        __nv_bfloat16* d = smp + st * 4 * PTILE;
        #pragma unroll
        for (int i = tid; i < 512; i += 256) {
            int r = i >> 2, c = (i & 3) * 8;
            cpa16(s2u(d + 0 * PTILE + r * LDSS + c), aH + (size_t)r * lda + k0 + c);
            cpa16(s2u(d + 1 * PTILE + r * LDSS + c), aL + (size_t)r * lda + k0 + c);
            cpa16(s2u(d + 2 * PTILE + r * LDSS + c), bH + (size_t)r * K + k0 + c);
            cpa16(s2u(d + 3 * PTILE + r * LDSS + c), bL + (size_t)r * K + k0 + c);
        }
    };

    auto compute = [&](int st) {
        const __nv_bfloat16* Ash = smp + st * 4 * PTILE;
        const __nv_bfloat16* Asl = Ash + PTILE;
        const __nv_bfloat16* Bsh = Asl + PTILE;
        const __nv_bfloat16* Bsl = Bsh + PTILE;
        #pragma unroll
        for (int ks = 0; ks < 2; ks++) {
            const int c = ks * 16;
            uint32_t ah[4][4], al[4][4], bh[2][4], bl[2][4];
            #pragma unroll
            for (int mt = 0; mt < 4; mt++) {
                int r = wm * 64 + mt * 16 + ar;
                ldsm4(ah[mt], s2u(Ash + r * LDSS + c + ac));
                ldsm4(al[mt], s2u(Asl + r * LDSS + c + ac));
            }
            #pragma unroll
            for (int np = 0; np < 2; np++) {
                int n = wn * 32 + np * 16 + br;
                ldsm4(bh[np], s2u(Bsh + n * LDSS + c + bc));
                ldsm4(bl[np], s2u(Bsl + n * LDSS + c + bc));
            }
            #pragma unroll
            for (int mt = 0; mt < 4; mt++)
                #pragma unroll
                for (int nt = 0; nt < 4; nt++) {
                    const uint32_t* bph = &bh[nt >> 1][(nt & 1) * 2];
                    const uint32_t* bpl = &bl[nt >> 1][(nt & 1) * 2];
                    mma16816(acc[mt][nt], ah[mt], bph);
                    mma16816(acc[mt][nt], ah[mt], bpl);
                    mma16816(acc[mt][nt], al[mt], bph);
                }
        }
    };

    const int nit = K / 32;
    stage(0, 0);  cpcommit();
    stage(1, 32); cpcommit();

    int st = 0;          // = it % 3
    for (int it = 0; it < nit; it++) {
        cpwait<1>();
        __syncthreads();
        compute(st);
        int st2 = st + 2; if (st2 >= 3) st2 -= 3;
        if (it + 2 < nit) stage(st2, (it + 2) * 32);
        cpcommit();
        if (++st == 3) st = 0;
    }

    #pragma unroll
    for (int mt = 0; mt < 4; mt++)
        #pragma unroll
        for (int nt = 0; nt < 4; nt++) {
            int r0 = row0 + wm * 64 + mt * 16 + (lane >> 2);
            int cc = col0 + wn * 32 + nt * 8 + ((lane & 3) << 1);
            float b0 = bias[cc], b1 = bias[cc + 1];
            #pragma unroll
            for (int half = 0; half < 2; half++) {
                int r = r0 + half * 8;
                float v0 = (acc[mt][nt][half * 2 + 0] + b0) * alpha;
                float v1 = (acc[mt][nt][half * 2 + 1] + b1) * alpha;
                if (OUT_SPLIT) {
                    uint32_t hi, lo;
                    split2(v0, v1, hi, lo);
                    *reinterpret_cast<uint32_t*>(&Ch[(size_t)r * ldc + cc]) = hi;
                    *reinterpret_cast<uint32_t*>(&Cl[(size_t)r * ldc + cc]) = lo;
                } else {
                    float2 o; o.x = v0; o.y = v1;
                    *reinterpret_cast<float2*>(&Cf[(size_t)r * ldc + cc]) = o;
                }
            }
        }
}

// ---------------------------------------------------------------------------
// Fused flash attention, 3-stage cp.async pipeline, exp2-domain softmax.
// Grid: (T/128, B*H). 256 threads = 8 warps; warp w owns t-rows [w*16, w*16+16).
// Q is pre-scaled by SCALING*log2(e); mask folded in via FFMA with log2(e).
// ---------------------------------------------------------------------------
static constexpr int LDK = 72;
static constexpr int LDV = 136;
static constexpr int KTILE = 128 * LDK;
static constexpr int VTILE = 64 * LDV;
static constexpr int FSTAGE = 2 * KTILE + 2 * VTILE;
static constexpr int FLASH_SMEM = 3 * FSTAGE * (int)sizeof(__nv_bfloat16);  // 215040

__global__ __launch_bounds__(256)
void flash_attn(const __nv_bfloat16* __restrict__ Qh, const __nv_bfloat16* __restrict__ Ql,
                const __nv_bfloat16* __restrict__ Kh, const __nv_bfloat16* __restrict__ Kl,
                const __nv_bfloat16* __restrict__ Vth, const __nv_bfloat16* __restrict__ Vtl,
                const float* __restrict__ mask, const float* __restrict__ head_mask,
                __nv_bfloat16* __restrict__ Ch, __nv_bfloat16* __restrict__ Cl)
{
    extern __shared__ __nv_bfloat16 smf[];   // [3][FSTAGE]

    const int tid = threadIdx.x, lane = tid & 31, wid = tid >> 5;
    const int z = blockIdx.y, bb = z >> 4, hh = z & 15;
    const int row0 = blockIdx.x * 128;
    const int tr = row0 + wid * 16 + (lane >> 2);

    const int g = lane >> 3, li = lane & 7;
    const int br = ((g >> 1) * 8) + li, bc = (g & 1) * 8;

    // ---- Q fragments (register-resident), k = 0..63; already log2e-scaled ----
    uint32_t qfh[4][4], qfl[4][4];
    {
        const size_t qrow = (size_t)(bb * T + tr) * EMB + hh * D;
        #pragma unroll
        for (int ks = 0; ks < 4; ks++) {
            const int c = ks * 16 + (lane & 3) * 2;
            qfh[ks][0] = ld32(Qh + qrow + c);
            qfh[ks][1] = ld32(Qh + qrow + (size_t)8 * EMB + c);
            qfh[ks][2] = ld32(Qh + qrow + c + 8);
            qfh[ks][3] = ld32(Qh + qrow + (size_t)8 * EMB + c + 8);
            qfl[ks][0] = ld32(Ql + qrow + c);
            qfl[ks][1] = ld32(Ql + qrow + (size_t)8 * EMB + c);
            qfl[ks][2] = ld32(Ql + qrow + c + 8);
            qfl[ks][3] = ld32(Ql + qrow + (size_t)8 * EMB + c + 8);
        }
    }

    float oacc[8][4] = {};
    float mrun[2] = {-1e30f, -1e30f};
    float lrun[2] = {0.0f, 0.0f};

    const __nv_bfloat16* kbase_h = Kh + (size_t)bb * S * EMB + hh * D;
    const __nv_bfloat16* kbase_l = Kl + (size_t)bb * S * EMB + hh * D;
    const __nv_bfloat16* vbase_h = Vth + (size_t)z * D * S;
    const __nv_bfloat16* vbase_l = Vtl + (size_t)z * D * S;
    const float* Mz = mask + (size_t)bb * T * S;

    auto stageKV = [&](int st, int s0) {
        __nv_bfloat16* kd  = smf + st * FSTAGE;
        __nv_bfloat16* kdl = kd + KTILE;
        __nv_bfloat16* vd  = kdl + KTILE;
        __nv_bfloat16* vdl = vd + VTILE;
        #pragma unroll
        for (int i = tid; i < 1024; i += 256) {
            int r = i >> 3, c = (i & 7) * 8;
            cpa16(s2u(kd  + r * LDK + c), kbase_h + (size_t)(s0 + r) * EMB + c);
            cpa16(s2u(kdl + r * LDK + c), kbase_l + (size_t)(s0 + r) * EMB + c);
        }
        #pragma unroll
        for (int i = tid; i < 1024; i += 256) {
            int r = i >> 4, c = (i & 15) * 8;
            cpa16(s2u(vd  + r * LDV + c), vbase_h + (size_t)r * S + s0 + c);
            cpa16(s2u(vdl + r * LDV + c), vbase_l + (size_t)r * S + s0 + c);
        }
    };

    stageKV(0, 0);   cpcommit();
    stageKV(1, 128); cpcommit();

    constexpr int NS = S / 128;
    int st = 0;                 // = is % 3
    for (int is = 0; is < NS; is++) {
        cpwait<1>();
        __syncthreads();

        const int s0 = is * 128;
        const __nv_bfloat16* Ksh = smf + st * FSTAGE;
        const __nv_bfloat16* Ksl = Ksh + KTILE;
        const __nv_bfloat16* Vsh = Ksl + KTILE;
        const __nv_bfloat16* Vsl = Vsh + VTILE;

        // ---- scores (log2 domain): 16(t) x 128(s) per warp ----
        float sacc[16][4] = {};
        #pragma unroll
        for (int ks = 0; ks < 4; ks++) {
            const int c = ks * 16;
            #pragma unroll
            for (int np = 0; np < 8; np++) {
                const int n = np * 16 + br;
                uint32_t kbh[4], kbl[4];
                ldsm4(kbh, s2u(Ksh + n * LDK + c + bc));
                ldsm4(kbl, s2u(Ksl + n * LDK + c + bc));
                mma16816(sacc[2 * np],     qfh[ks], kbh);
                mma16816(sacc[2 * np],     qfh[ks], kbl);
                mma16816(sacc[2 * np],     qfl[ks], kbh);
                mma16816(sacc[2 * np + 1], qfh[ks], kbh + 2);
                mma16816(sacc[2 * np + 1], qfh[ks], kbl + 2);
                mma16816(sacc[2 * np + 1], qfl[ks], kbh + 2);
            }
        }

        // ---- + mask * log2e (FFMA) ----
        #pragma unroll
        for (int nt = 0; nt < 16; nt++) {
            const int cg = s0 + nt * 8 + (lane & 3) * 2;
            float2 m0 = *reinterpret_cast<const float2*>(&Mz[(size_t)tr * S + cg]);
            float2 m1 = *reinterpret_cast<const float2*>(&Mz[(size_t)(tr + 8) * S + cg]);
            sacc[nt][0] = fmaf(m0.x, LOG2E, sacc[nt][0]);
            sacc[nt][1] = fmaf(m0.y, LOG2E, sacc[nt][1]);
            sacc[nt][2] = fmaf(m1.x, LOG2E, sacc[nt][2]);
            sacc[nt][3] = fmaf(m1.y, LOG2E, sacc[nt][3]);
        }

        // ---- online softmax in exp2 domain (per row-half) ----
        #pragma unroll
        for (int hf = 0; hf < 2; hf++) {
            float vm = -1e30f;
            #pragma unroll
            for (int nt = 0; nt < 16; nt++)
                vm = fmaxf(vm, fmaxf(sacc[nt][hf * 2], sacc[nt][hf * 2 + 1]));
            vm = fmaxf(vm, __shfl_xor_sync(0xffffffffu, vm, 1));
            vm = fmaxf(vm, __shfl_xor_sync(0xffffffffu, vm, 2));
            const float mnew = fmaxf(mrun[hf], vm);
            const float f = ex2(mrun[hf] - mnew);
            mrun[hf] = mnew;
            lrun[hf] *= f;
            #pragma unroll
            for (int nt = 0; nt < 8; nt++) {
                oacc[nt][hf * 2 + 0] *= f;
                oacc[nt][hf * 2 + 1] *= f;
            }
            float ls = 0.0f;
            #pragma unroll
            for (int nt = 0; nt < 16; nt++) {
                float e0 = ex2(sacc[nt][hf * 2 + 0] - mnew);
                float e1 = ex2(sacc[nt][hf * 2 + 1] - mnew);
                sacc[nt][hf * 2 + 0] = e0;
                sacc[nt][hf * 2 + 1] = e1;
                ls += e0 + e1;
            }
            lrun[hf] += ls;
        }

        // ---- PV: O(16t x 64d) += P(16t x 128s) @ Vt(64d x 128s)^T ----
        #pragma unroll
        for (int ks = 0; ks < 8; ks++) {
            uint32_t ph[4], pl[4];
            split2(sacc[2 * ks][0],     sacc[2 * ks][1],     ph[0], pl[0]);
            split2(sacc[2 * ks][2],     sacc[2 * ks][3],     ph[1], pl[1]);
            split2(sacc[2 * ks + 1][0], sacc[2 * ks + 1][1], ph[2], pl[2]);
            split2(sacc[2 * ks + 1][2], sacc[2 * ks + 1][3], ph[3], pl[3]);
            const int c = ks * 16;
            #pragma unroll
            for (int np = 0; np < 4; np++) {
                const int n = np * 16 + br;
                uint32_t vbh[4], vbl[4];
                ldsm4(vbh, s2u(Vsh + n * LDV + c + bc));
                ldsm4(vbl, s2u(Vsl + n * LDV + c + bc));
                mma16816(oacc[2 * np],     ph, vbh);
                mma16816(oacc[2 * np],     ph, vbl);
                mma16816(oacc[2 * np],     pl, vbh);
                mma16816(oacc[2 * np + 1], ph, vbh + 2);
                mma16816(oacc[2 * np + 1], ph, vbl + 2);
                mma16816(oacc[2 * np + 1], pl, vbh + 2);
            }
        }

        // stage tile is+2 into buffer (st+2)%3 (last read at iter is-1; safe
        // because all warps passed this iteration's __syncthreads)
        int st2 = st + 2; if (st2 >= 3) st2 -= 3;
        if (is + 2 < NS) stageKV(st2, (is + 2) * 128);
        cpcommit();
        if (++st == 3) st = 0;
    }

    // ---- epilogue: normalize, head-mask scale, split to ctx hi/lo ----
    float scale[2];
    #pragma unroll
    for (int hf = 0; hf < 2; hf++) {
        float l = lrun[hf];
        l += __shfl_xor_sync(0xffffffffu, l, 1);
        l += __shfl_xor_sync(0xffffffffu, l, 2);
        scale[hf] = head_mask[hh] / l;
    }
    #pragma unroll
    for (int nt = 0; nt < 8; nt++) {
        const int cc = hh * D + nt * 8 + (lane & 3) * 2;
        #pragma unroll
        for (int hf = 0; hf < 2; hf++) {
            const size_t r = (size_t)(bb * T + tr + hf * 8);
            uint32_t hi, lo;
            split2(oacc[nt][hf * 2 + 0] * scale[hf],
                   oacc[nt][hf * 2 + 1] * scale[hf], hi, lo);
            *reinterpret_cast<uint32_t*>(&Ch[r * EMB + cc]) = hi;
            *reinterpret_cast<uint32_t*>(&Cl[r * EMB + cc]) = lo;
        }
    }
}

// ---------------------------------------------------------------------------
extern "C" void kernel_launch(void* const* d_in, const int* in_sizes, int n_in,
                              void* d_out, int out_size)
{
    const float* hs   = (const float*)d_in[0];
    const float* kv   = (const float*)d_in[1];
    const float* mask = (const float*)d_in[2];
    const float* hm   = (const float*)d_in[3];
    const float* Wq   = (const float*)d_in[4];
    const float* bq   = (const float*)d_in[5];
    const float* Wk   = (const float*)d_in[6];
    const float* bk   = (const float*)d_in[7];
    const float* Wv   = (const float*)d_in[8];
    const float* bv   = (const float*)d_in[9];
    const float* Wo   = (const float*)d_in[10];
    const float* bo   = (const float*)d_in[11];
    float* out = (float*)d_out;

    __nv_bfloat16 *HSh, *HSl, *KVh, *KVl;
    __nv_bfloat16 *Qh, *Ql, *Kh, *Kl, *Vh, *Vl, *Vth, *Vtl, *Ch, *Cl;
    __nv_bfloat16 *Wqh, *Wql, *Wkh, *Wkl, *Wvh, *Wvl, *Woh, *Wol;
    cudaGetSymbolAddress((void**)&HSh, g_HShi); cudaGetSymbolAddress((void**)&HSl, g_HSlo);
    cudaGetSymbolAddress((void**)&KVh, g_KVhi); cudaGetSymbolAddress((void**)&KVl, g_KVlo);
    cudaGetSymbolAddress((void**)&Qh, g_Qhi);  cudaGetSymbolAddress((void**)&Ql, g_Qlo);
    cudaGetSymbolAddress((void**)&Kh, g_Khi);  cudaGetSymbolAddress((void**)&Kl, g_Klo);
    cudaGetSymbolAddress((void**)&Vh, g_Vhi);  cudaGetSymbolAddress((void**)&Vl, g_Vlo);
    cudaGetSymbolAddress((void**)&Vth, g_Vthi); cudaGetSymbolAddress((void**)&Vtl, g_Vtlo);
    cudaGetSymbolAddress((void**)&Ch, g_Chi);  cudaGetSymbolAddress((void**)&Cl, g_Clo);
    cudaGetSymbolAddress((void**)&Wqh, g_Wqthi); cudaGetSymbolAddress((void**)&Wql, g_Wqtlo);
    cudaGetSymbolAddress((void**)&Wkh, g_Wkthi); cudaGetSymbolAddress((void**)&Wkl, g_Wktlo);
    cudaGetSymbolAddress((void**)&Wvh, g_Wvthi); cudaGetSymbolAddress((void**)&Wvl, g_Wvtlo);
    cudaGetSymbolAddress((void**)&Woh, g_Wothi); cudaGetSymbolAddress((void**)&Wol, g_Wotlo);

    cudaFuncSetAttribute(proj_nt<true>,  cudaFuncAttributeMaxDynamicSharedMemorySize, PROJ_SMEM);
    cudaFuncSetAttribute(proj_nt<false>, cudaFuncAttributeMaxDynamicSharedMemorySize, PROJ_SMEM);
    cudaFuncSetAttribute(flash_attn, cudaFuncAttributeMaxDynamicSharedMemorySize, FLASH_SMEM);

    // Split activations fp32 -> bf16 hi/lo
    split_act<<<(B * T * QIN / 4 + 255) / 256, 256>>>(hs, HSh, HSl, B * T * QIN / 4);
    split_act<<<(B * S * KVIN / 4 + 255) / 256, 256>>>(kv, KVh, KVl, B * S * KVIN / 4);

    // Weight transpose + split
    wsplit_t<<<dim3(EMB / 32, QIN / 32), 256>>>(Wq, QIN, EMB, Wqh, Wql);
    wsplit_t<<<dim3(EMB / 32, KVIN / 32), 256>>>(Wk, KVIN, EMB, Wkh, Wkl);
    wsplit_t<<<dim3(EMB / 32, KVIN / 32), 256>>>(Wv, KVIN, EMB, Wvh, Wvl);
    wsplit_t<<<dim3(EMB / 32, EMB / 32), 256>>>(Wo, EMB, EMB, Woh, Wol);

    // Projections -> split bf16 (Q pre-scaled by SCALING * log2e for exp2 softmax)
    proj_nt<true><<<dim3(EMB / 128, (B * T) / 128), 256, PROJ_SMEM>>>(
        QIN, HSh, HSl, QIN, Wqh, Wql, nullptr, Qh, Ql, EMB, bq, SCALING * LOG2E);
    proj_nt<true><<<dim3(EMB / 128, (B * S) / 128), 256, PROJ_SMEM>>>(
        KVIN, KVh, KVl, KVIN, Wkh, Wkl, nullptr, Kh, Kl, EMB, bk, 1.0f);
    proj_nt<true><<<dim3(EMB / 128, (B * S) / 128), 256, PROJ_SMEM>>>(
        KVIN, KVh, KVl, KVIN, Wvh, Wvl, nullptr, Vh, Vl, EMB, bv, 1.0f);

    // V transpose per head
    vtrans<<<dim3(S / 64, 1, B * H), 256>>>(Vh, Vl, Vth, Vtl);

    // Fused scores + softmax + PV
    flash_attn<<<dim3(T / 128, B * H), 256, FLASH_SMEM>>>(
        Qh, Ql, Kh, Kl, Vth, Vtl, mask, hm, Ch, Cl);

    // out = ctx @ Wo + bo
    proj_nt<false><<<dim3(EMB / 128, (B * T) / 128), 256, PROJ_SMEM>>>(
        EMB, Ch, Cl, EMB, Woh, Wol, out, nullptr, nullptr, EMB, bo, 1.0f);
}

// round 12
// speedup vs baseline: 1.0043x; 1.0043x over previous
#include <cuda_runtime.h>
#include <cuda_bf16.h>
#include <cstdint>

// Problem constants
static constexpr int B   = 8;
static constexpr int T   = 1024;
static constexpr int S   = 1024;
static constexpr int H   = 16;
static constexpr int D   = 64;
static constexpr int EMB = 1024;
static constexpr int QIN = 1024;
static constexpr int KVIN = 256;
static constexpr float SCALING = 0.125f;
static constexpr float LOG2E = 1.4426950408889634f;

// ---------------------------------------------------------------------------
// Scratch (__device__ globals; allocation-free rule)
// ---------------------------------------------------------------------------
__device__ __nv_bfloat16 g_HShi[B * T * QIN],  g_HSlo[B * T * QIN];      // split hs
__device__ __nv_bfloat16 g_KVhi[B * S * KVIN], g_KVlo[B * S * KVIN];     // split kv

__device__ __nv_bfloat16 g_Qhi[B * T * EMB], g_Qlo[B * T * EMB];
__device__ __nv_bfloat16 g_Khi[B * S * EMB], g_Klo[B * S * EMB];
__device__ __nv_bfloat16 g_Vhi[B * S * EMB], g_Vlo[B * S * EMB];
__device__ __nv_bfloat16 g_Vthi[B * H * D * S], g_Vtlo[B * H * D * S];   // [z*D+d][S]
__device__ __nv_bfloat16 g_Chi[B * T * EMB], g_Clo[B * T * EMB];         // ctx

__device__ __nv_bfloat16 g_Wqthi[EMB * QIN],  g_Wqtlo[EMB * QIN];        // [N][K]
__device__ __nv_bfloat16 g_Wkthi[EMB * KVIN], g_Wktlo[EMB * KVIN];
__device__ __nv_bfloat16 g_Wvthi[EMB * KVIN], g_Wvtlo[EMB * KVIN];
__device__ __nv_bfloat16 g_Wothi[EMB * EMB],  g_Wotlo[EMB * EMB];

// ---------------------------------------------------------------------------
// Low-level helpers
// ---------------------------------------------------------------------------
static constexpr int LDSS = 40;   // smem row stride (bf16) for 32-col proj tiles

__device__ __forceinline__ uint32_t ld32(const __nv_bfloat16* p) {
    return *reinterpret_cast<const uint32_t*>(p);
}
__device__ __forceinline__ uint32_t s2u(const void* p) {
    return (uint32_t)__cvta_generic_to_shared(p);
}
__device__ __forceinline__ void cpa16(uint32_t dst, const void* src) {
    asm volatile("cp.async.cg.shared.global [%0], [%1], 16;\n" :: "r"(dst), "l"(src));
}
__device__ __forceinline__ void cpcommit() {
    asm volatile("cp.async.commit_group;\n");
}
template <int N> __device__ __forceinline__ void cpwait() {
    asm volatile("cp.async.wait_group %0;\n" :: "n"(N));
}
__device__ __forceinline__ void ldsm4(uint32_t* r, uint32_t a) {
    asm volatile("ldmatrix.sync.aligned.m8n8.x4.shared.b16 {%0,%1,%2,%3}, [%4];\n"
                 : "=r"(r[0]), "=r"(r[1]), "=r"(r[2]), "=r"(r[3]) : "r"(a));
}
__device__ __forceinline__ void mma16816(float* c, const uint32_t* a, const uint32_t* b) {
    asm volatile(
        "mma.sync.aligned.m16n8k16.row.col.f32.bf16.bf16.f32 "
        "{%0,%1,%2,%3}, {%4,%5,%6,%7}, {%8,%9}, {%0,%1,%2,%3};\n"
        : "+f"(c[0]), "+f"(c[1]), "+f"(c[2]), "+f"(c[3])
        : "r"(a[0]), "r"(a[1]), "r"(a[2]), "r"(a[3]), "r"(b[0]), "r"(b[1]));
}
__device__ __forceinline__ float ex2(float x) {
    float y;
    asm("ex2.approx.f32 %0, %1;" : "=f"(y) : "f"(x));
    return y;
}
__device__ __forceinline__ uint32_t pack_bf16(float v0, float v1) {
    __nv_bfloat162 p;
    p.x = __float2bfloat16(v0);
    p.y = __float2bfloat16(v1);
    return *reinterpret_cast<uint32_t*>(&p);
}
__device__ __forceinline__ void split2(float v0, float v1, uint32_t& hi, uint32_t& lo) {
    __nv_bfloat16 h0 = __float2bfloat16(v0), h1 = __float2bfloat16(v1);
    __nv_bfloat16 l0 = __float2bfloat16(v0 - __bfloat162float(h0));
    __nv_bfloat16 l1 = __float2bfloat16(v1 - __bfloat162float(h1));
    __nv_bfloat162 hp; hp.x = h0; hp.y = h1;
    __nv_bfloat162 lp; lp.x = l0; lp.y = l1;
    hi = *reinterpret_cast<uint32_t*>(&hp);
    lo = *reinterpret_cast<uint32_t*>(&lp);
}

// ---------------------------------------------------------------------------
// Activation split: fp32 -> bf16 hi/lo (elementwise, vectorized)
// ---------------------------------------------------------------------------
__global__ __launch_bounds__(256)
void split_act(const float* __restrict__ x,
               __nv_bfloat16* __restrict__ xh, __nv_bfloat16* __restrict__ xl, int n4)
{
    int i = blockIdx.x * 256 + threadIdx.x;
    if (i >= n4) return;
    float4 v = reinterpret_cast<const float4*>(x)[i];
    float vv[4] = {v.x, v.y, v.z, v.w};
    __align__(8) __nv_bfloat16 h[4], l[4];
    #pragma unroll
    for (int j = 0; j < 4; j++) {
        h[j] = __float2bfloat16(vv[j]);
        l[j] = __float2bfloat16(vv[j] - __bfloat162float(h[j]));
    }
    reinterpret_cast<uint2*>(xh)[i] = *reinterpret_cast<uint2*>(h);
    reinterpret_cast<uint2*>(xl)[i] = *reinterpret_cast<uint2*>(l);
}

// ---------------------------------------------------------------------------
// Weight transpose + split: W [K,N] fp32 -> Wt_hi/lo [N,K] bf16
// ---------------------------------------------------------------------------
__global__ __launch_bounds__(256)
void wsplit_t(const float* __restrict__ W, int K, int N,
              __nv_bfloat16* __restrict__ Whi, __nv_bfloat16* __restrict__ Wlo)
{
    __shared__ float sm[32][33];
    const int k0 = blockIdx.y * 32, n0 = blockIdx.x * 32;
    const int tid = threadIdx.x;

    for (int i = tid; i < 32 * 8; i += 256) {
        int r = i >> 3, c4 = i & 7;
        float4 v = *reinterpret_cast<const float4*>(&W[(size_t)(k0 + r) * N + n0 + c4 * 4]);
        sm[r][c4 * 4 + 0] = v.x; sm[r][c4 * 4 + 1] = v.y;
        sm[r][c4 * 4 + 2] = v.z; sm[r][c4 * 4 + 3] = v.w;
    }
    __syncthreads();
    for (int i = tid; i < 32 * 8; i += 256) {
        int n = i >> 3, k4 = i & 7;
        __align__(8) __nv_bfloat16 h[4], l[4];
        #pragma unroll
        for (int j = 0; j < 4; j++) {
            float v = sm[k4 * 4 + j][n];
            h[j] = __float2bfloat16(v);
            l[j] = __float2bfloat16(v - __bfloat162float(h[j]));
        }
        *reinterpret_cast<uint2*>(&Whi[(size_t)(n0 + n) * K + k0 + k4 * 4]) = *reinterpret_cast<uint2*>(h);
        *reinterpret_cast<uint2*>(&Wlo[(size_t)(n0 + n) * K + k0 + k4 * 4]) = *reinterpret_cast<uint2*>(l);
    }
}

// ---------------------------------------------------------------------------
// V transpose (bf16): V [b*S+s][h*D+d] -> Vt [(b*H+h)*D+d][s]
// ---------------------------------------------------------------------------
__global__ __launch_bounds__(256)
void vtrans(const __nv_bfloat16* __restrict__ Vh, const __nv_bfloat16* __restrict__ Vl,
            __nv_bfloat16* __restrict__ Vth, __nv_bfloat16* __restrict__ Vtl)
{
    __shared__ __nv_bfloat16 sm[64][72];
    const int z = blockIdx.z, bb = z >> 4, hh = z & 15;
    const int s0 = blockIdx.x * 64;

    #pragma unroll
    for (int p = 0; p < 2; p++) {
        const __nv_bfloat16* src = p ? Vl : Vh;
        __nv_bfloat16* dst = p ? Vtl : Vth;
        const __nv_bfloat16* sp = src + (size_t)(bb * S + s0) * EMB + hh * D;
        for (int i = threadIdx.x; i < 64 * 16; i += 256) {
            int s = i >> 4, d4 = i & 15;
            *reinterpret_cast<uint2*>(&sm[s][d4 * 4]) =
                *reinterpret_cast<const uint2*>(&sp[(size_t)s * EMB + d4 * 4]);
        }
        __syncthreads();
        __nv_bfloat16* dp = dst + (size_t)z * D * S + s0;
        for (int i = threadIdx.x; i < 64 * 16; i += 256) {
            int d = i >> 4, s4 = i & 15;
            __align__(8) __nv_bfloat16 t[4];
            t[0] = sm[s4 * 4 + 0][d]; t[1] = sm[s4 * 4 + 1][d];
            t[2] = sm[s4 * 4 + 2][d]; t[3] = sm[s4 * 4 + 3][d];
            *reinterpret_cast<uint2*>(&dp[(size_t)d * S + s4 * 4]) = *reinterpret_cast<uint2*>(t);
        }
        __syncthreads();
    }
}

// ---------------------------------------------------------------------------
// Projection GEMM (NT), split-bf16 3-MMA, 2-stage cp.async pipeline + ldmatrix.
// (R8 structure: 81920 B smem -> 2 CTAs/SM.)
// C[M,N] = (A[M,K] @ Bt[N,K]^T + bias) * alpha
// BM=BN=128, BK=32, 256 threads (8 warps 2x4), warp tile 64x32.
// ---------------------------------------------------------------------------
static constexpr int PTILE = 128 * LDSS;
static constexpr int PROJ_SMEM = 2 * 4 * PTILE * (int)sizeof(__nv_bfloat16);  // 81920

template <bool OUT_SPLIT>
__global__ __launch_bounds__(256)
void proj_nt(int K,
             const __nv_bfloat16* __restrict__ Ah, const __nv_bfloat16* __restrict__ Al,
             int lda,
             const __nv_bfloat16* __restrict__ Bth, const __nv_bfloat16* __restrict__ Btl,
             float* __restrict__ Cf,
             __nv_bfloat16* __restrict__ Ch, __nv_bfloat16* __restrict__ Cl,
             int ldc, const float* __restrict__ bias, float alpha)
{
    extern __shared__ __nv_bfloat16 smp[];   // [2][4][PTILE]

    const int tid = threadIdx.x, lane = tid & 31, wid = tid >> 5;
    const int wm = wid >> 2, wn = wid & 3;
    const int row0 = blockIdx.y * 128, col0 = blockIdx.x * 128;

    const __nv_bfloat16* aH = Ah + (size_t)row0 * lda;
    const __nv_bfloat16* aL = Al + (size_t)row0 * lda;
    const __nv_bfloat16* bH = Bth + (size_t)col0 * K;
    const __nv_bfloat16* bL = Btl + (size_t)col0 * K;

    const int g = lane >> 3, li = lane & 7;
    const int ar = ((g & 1) * 8) + li, ac = (g >> 1) * 8;   // A-frag ldmatrix lane map
    const int br = ((g >> 1) * 8) + li, bc = (g & 1) * 8;   // B-frag ldmatrix lane map

    float acc[4][4][4] = {};

    auto stage = [&](int st, int k0) {
        __nv_bfloat16* d = smp + st * 4 * PTILE;
        #pragma unroll
        for (int i = tid; i < 512; i += 256) {
            int r = i >> 2, c = (i & 3) * 8;
            cpa16(s2u(d + 0 * PTILE + r * LDSS + c), aH + (size_t)r * lda + k0 + c);
            cpa16(s2u(d + 1 * PTILE + r * LDSS + c), aL + (size_t)r * lda + k0 + c);
            cpa16(s2u(d + 2 * PTILE + r * LDSS + c), bH + (size_t)r * K + k0 + c);
            cpa16(s2u(d + 3 * PTILE + r * LDSS + c), bL + (size_t)r * K + k0 + c);
        }
    };

    auto compute = [&](int st) {
        const __nv_bfloat16* Ash = smp + st * 4 * PTILE;
        const __nv_bfloat16* Asl = Ash + PTILE;
        const __nv_bfloat16* Bsh = Asl + PTILE;
        const __nv_bfloat16* Bsl = Bsh + PTILE;
        #pragma unroll
        for (int ks = 0; ks < 2; ks++) {
            const int c = ks * 16;
            uint32_t ah[4][4], al[4][4], bh[2][4], bl[2][4];
            #pragma unroll
            for (int mt = 0; mt < 4; mt++) {
                int r = wm * 64 + mt * 16 + ar;
                ldsm4(ah[mt], s2u(Ash + r * LDSS + c + ac));
                ldsm4(al[mt], s2u(Asl + r * LDSS + c + ac));
            }
            #pragma unroll
            for (int np = 0; np < 2; np++) {
                int n = wn * 32 + np * 16 + br;
                ldsm4(bh[np], s2u(Bsh + n * LDSS + c + bc));
                ldsm4(bl[np], s2u(Bsl + n * LDSS + c + bc));
            }
            #pragma unroll
            for (int mt = 0; mt < 4; mt++)
                #pragma unroll
                for (int nt = 0; nt < 4; nt++) {
                    const uint32_t* bph = &bh[nt >> 1][(nt & 1) * 2];
                    const uint32_t* bpl = &bl[nt >> 1][(nt & 1) * 2];
                    mma16816(acc[mt][nt], ah[mt], bph);
                    mma16816(acc[mt][nt], ah[mt], bpl);
                    mma16816(acc[mt][nt], al[mt], bph);
                }
        }
    };

    const int nit = K / 32;
    stage(0, 0);
    cpcommit();
    for (int it = 0; it < nit; it++) {
        if (it + 1 < nit) { stage((it + 1) & 1, (it + 1) * 32); cpcommit(); }
        if (it + 1 < nit) cpwait<1>(); else cpwait<0>();
        __syncthreads();
        compute(it & 1);
        __syncthreads();
    }

    #pragma unroll
    for (int mt = 0; mt < 4; mt++)
        #pragma unroll
        for (int nt = 0; nt < 4; nt++) {
            int r0 = row0 + wm * 64 + mt * 16 + (lane >> 2);
            int cc = col0 + wn * 32 + nt * 8 + ((lane & 3) << 1);
            float b0 = bias[cc], b1 = bias[cc + 1];
            #pragma unroll
            for (int half = 0; half < 2; half++) {
                int r = r0 + half * 8;
                float v0 = (acc[mt][nt][half * 2 + 0] + b0) * alpha;
                float v1 = (acc[mt][nt][half * 2 + 1] + b1) * alpha;
                if (OUT_SPLIT) {
                    uint32_t hi, lo;
                    split2(v0, v1, hi, lo);
                    *reinterpret_cast<uint32_t*>(&Ch[(size_t)r * ldc + cc]) = hi;
                    *reinterpret_cast<uint32_t*>(&Cl[(size_t)r * ldc + cc]) = lo;
                } else {
                    float2 o; o.x = v0; o.y = v1;
                    *reinterpret_cast<float2*>(&Cf[(size_t)r * ldc + cc]) = o;
                }
            }
        }
}

// ---------------------------------------------------------------------------
// Fused flash attention, 3-stage cp.async pipeline, exp2-domain softmax.
// PV uses bf16-rounded P (2-term: P*Vhi + P*Vlo) — error ~1e-5 global.
// Grid: (T/128, B*H). 256 threads = 8 warps; warp w owns t-rows [w*16, w*16+16).
// ---------------------------------------------------------------------------
static constexpr int LDK = 72;
static constexpr int LDV = 136;
static constexpr int KTILE = 128 * LDK;
static constexpr int VTILE = 64 * LDV;
static constexpr int FSTAGE = 2 * KTILE + 2 * VTILE;
static constexpr int FLASH_SMEM = 3 * FSTAGE * (int)sizeof(__nv_bfloat16);  // 215040

__global__ __launch_bounds__(256)
void flash_attn(const __nv_bfloat16* __restrict__ Qh, const __nv_bfloat16* __restrict__ Ql,
                const __nv_bfloat16* __restrict__ Kh, const __nv_bfloat16* __restrict__ Kl,
                const __nv_bfloat16* __restrict__ Vth, const __nv_bfloat16* __restrict__ Vtl,
                const float* __restrict__ mask, const float* __restrict__ head_mask,
                __nv_bfloat16* __restrict__ Ch, __nv_bfloat16* __restrict__ Cl)
{
    extern __shared__ __nv_bfloat16 smf[];   // [3][FSTAGE]

    const int tid = threadIdx.x, lane = tid & 31, wid = tid >> 5;
    const int z = blockIdx.y, bb = z >> 4, hh = z & 15;
    const int row0 = blockIdx.x * 128;
    const int tr = row0 + wid * 16 + (lane >> 2);

    const int g = lane >> 3, li = lane & 7;
    const int br = ((g >> 1) * 8) + li, bc = (g & 1) * 8;

    // ---- Q fragments (register-resident), k = 0..63; already log2e-scaled ----
    uint32_t qfh[4][4], qfl[4][4];
    {
        const size_t qrow = (size_t)(bb * T + tr) * EMB + hh * D;
        #pragma unroll
        for (int ks = 0; ks < 4; ks++) {
            const int c = ks * 16 + (lane & 3) * 2;
            qfh[ks][0] = ld32(Qh + qrow + c);
            qfh[ks][1] = ld32(Qh + qrow + (size_t)8 * EMB + c);
            qfh[ks][2] = ld32(Qh + qrow + c + 8);
            qfh[ks][3] = ld32(Qh + qrow + (size_t)8 * EMB + c + 8);
            qfl[ks][0] = ld32(Ql + qrow + c);
            qfl[ks][1] = ld32(Ql + qrow + (size_t)8 * EMB + c);
            qfl[ks][2] = ld32(Ql + qrow + c + 8);
            qfl[ks][3] = ld32(Ql + qrow + (size_t)8 * EMB + c + 8);
        }
    }

    float oacc[8][4] = {};
    float mrun[2] = {-1e30f, -1e30f};
    float lrun[2] = {0.0f, 0.0f};

    const __nv_bfloat16* kbase_h = Kh + (size_t)bb * S * EMB + hh * D;
    const __nv_bfloat16* kbase_l = Kl + (size_t)bb * S * EMB + hh * D;
    const __nv_bfloat16* vbase_h = Vth + (size_t)z * D * S;
    const __nv_bfloat16* vbase_l = Vtl + (size_t)z * D * S;
    const float* Mz = mask + (size_t)bb * T * S;

    auto stageKV = [&](int st, int s0) {
        __nv_bfloat16* kd  = smf + st * FSTAGE;
        __nv_bfloat16* kdl = kd + KTILE;
        __nv_bfloat16* vd  = kdl + KTILE;
        __nv_bfloat16* vdl = vd + VTILE;
        #pragma unroll
        for (int i = tid; i < 1024; i += 256) {
            int r = i >> 3, c = (i & 7) * 8;
            cpa16(s2u(kd  + r * LDK + c), kbase_h + (size_t)(s0 + r) * EMB + c);
            cpa16(s2u(kdl + r * LDK + c), kbase_l + (size_t)(s0 + r) * EMB + c);
        }
        #pragma unroll
        for (int i = tid; i < 1024; i += 256) {
            int r = i >> 4, c = (i & 15) * 8;
            cpa16(s2u(vd  + r * LDV + c), vbase_h + (size_t)r * S + s0 + c);
            cpa16(s2u(vdl + r * LDV + c), vbase_l + (size_t)r * S + s0 + c);
        }
    };

    stageKV(0, 0);   cpcommit();
    stageKV(1, 128); cpcommit();

    constexpr int NS = S / 128;
    int st = 0;                 // = is % 3
    for (int is = 0; is < NS; is++) {
        cpwait<1>();
        __syncthreads();

        const int s0 = is * 128;
        const __nv_bfloat16* Ksh = smf + st * FSTAGE;
        const __nv_bfloat16* Ksl = Ksh + KTILE;
        const __nv_bfloat16* Vsh = Ksl + KTILE;
        const __nv_bfloat16* Vsl = Vsh + VTILE;

        // ---- scores (log2 domain): 16(t) x 128(s) per warp ----
        float sacc[16][4] = {};
        #pragma unroll
        for (int ks = 0; ks < 4; ks++) {
            const int c = ks * 16;
            #pragma unroll
            for (int np = 0; np < 8; np++) {
                const int n = np * 16 + br;
                uint32_t kbh[4], kbl[4];
                ldsm4(kbh, s2u(Ksh + n * LDK + c + bc));
                ldsm4(kbl, s2u(Ksl + n * LDK + c + bc));
                mma16816(sacc[2 * np],     qfh[ks], kbh);
                mma16816(sacc[2 * np],     qfh[ks], kbl);
                mma16816(sacc[2 * np],     qfl[ks], kbh);
                mma16816(sacc[2 * np + 1], qfh[ks], kbh + 2);
                mma16816(sacc[2 * np + 1], qfh[ks], kbl + 2);
                mma16816(sacc[2 * np + 1], qfl[ks], kbh + 2);
            }
        }

        // ---- + mask * log2e (FFMA) ----
        #pragma unroll
        for (int nt = 0; nt < 16; nt++) {
            const int cg = s0 + nt * 8 + (lane & 3) * 2;
            float2 m0 = *reinterpret_cast<const float2*>(&Mz[(size_t)tr * S + cg]);
            float2 m1 = *reinterpret_cast<const float2*>(&Mz[(size_t)(tr + 8) * S + cg]);
            sacc[nt][0] = fmaf(m0.x, LOG2E, sacc[nt][0]);
            sacc[nt][1] = fmaf(m0.y, LOG2E, sacc[nt][1]);
            sacc[nt][2] = fmaf(m1.x, LOG2E, sacc[nt][2]);
            sacc[nt][3] = fmaf(m1.y, LOG2E, sacc[nt][3]);
        }

        // ---- online softmax in exp2 domain (per row-half) ----
        #pragma unroll
        for (int hf = 0; hf < 2; hf++) {
            float vm = -1e30f;
            #pragma unroll
            for (int nt = 0; nt < 16; nt++)
                vm = fmaxf(vm, fmaxf(sacc[nt][hf * 2], sacc[nt][hf * 2 + 1]));
            vm = fmaxf(vm, __shfl_xor_sync(0xffffffffu, vm, 1));
            vm = fmaxf(vm, __shfl_xor_sync(0xffffffffu, vm, 2));
            const float mnew = fmaxf(mrun[hf], vm);
            const float f = ex2(mrun[hf] - mnew);
            mrun[hf] = mnew;
            lrun[hf] *= f;
            #pragma unroll
            for (int nt = 0; nt < 8; nt++) {
                oacc[nt][hf * 2 + 0] *= f;
                oacc[nt][hf * 2 + 1] *= f;
            }
            float ls = 0.0f;
            #pragma unroll
            for (int nt = 0; nt < 16; nt++) {
                float e0 = ex2(sacc[nt][hf * 2 + 0] - mnew);
                float e1 = ex2(sacc[nt][hf * 2 + 1] - mnew);
                sacc[nt][hf * 2 + 0] = e0;
                sacc[nt][hf * 2 + 1] = e1;
                ls += e0 + e1;
            }
            lrun[hf] += ls;
        }

        // ---- PV: O(16t x 64d) += P_bf16(16t x 128s) @ (Vhi+Vlo)(64d x 128s)^T ----
        #pragma unroll
        for (int ks = 0; ks < 8; ks++) {
            uint32_t ph[4];
            ph[0] = pack_bf16(sacc[2 * ks][0],     sacc[2 * ks][1]);
            ph[1] = pack_bf16(sacc[2 * ks][2],     sacc[2 * ks][3]);
            ph[2] = pack_bf16(sacc[2 * ks + 1][0], sacc[2 * ks + 1][1]);
            ph[3] = pack_bf16(sacc[2 * ks + 1][2], sacc[2 * ks + 1][3]);
            const int c = ks * 16;
            #pragma unroll
            for (int np = 0; np < 4; np++) {
                const int n = np * 16 + br;
                uint32_t vbh[4], vbl[4];
                ldsm4(vbh, s2u(Vsh + n * LDV + c + bc));
                ldsm4(vbl, s2u(Vsl + n * LDV + c + bc));
                mma16816(oacc[2 * np],     ph, vbh);
                mma16816(oacc[2 * np],     ph, vbl);
                mma16816(oacc[2 * np + 1], ph, vbh + 2);
                mma16816(oacc[2 * np + 1], ph, vbl + 2);
            }
        }

        // stage tile is+2 into buffer (st+2)%3 (last read at iter is-1; safe
        // because all warps passed this iteration's __syncthreads)
        int st2 = st + 2; if (st2 >= 3) st2 -= 3;
        if (is + 2 < NS) stageKV(st2, (is + 2) * 128);
        cpcommit();
        if (++st == 3) st = 0;
    }

    // ---- epilogue: normalize, head-mask scale, split to ctx hi/lo ----
    float scale[2];
    #pragma unroll
    for (int hf = 0; hf < 2; hf++) {
        float l = lrun[hf];
        l += __shfl_xor_sync(0xffffffffu, l, 1);
        l += __shfl_xor_sync(0xffffffffu, l, 2);
        scale[hf] = head_mask[hh] / l;
    }
    #pragma unroll
    for (int nt = 0; nt < 8; nt++) {
        const int cc = hh * D + nt * 8 + (lane & 3) * 2;
        #pragma unroll
        for (int hf = 0; hf < 2; hf++) {
            const size_t r = (size_t)(bb * T + tr + hf * 8);
            uint32_t hi, lo;
            split2(oacc[nt][hf * 2 + 0] * scale[hf],
                   oacc[nt][hf * 2 + 1] * scale[hf], hi, lo);
            *reinterpret_cast<uint32_t*>(&Ch[r * EMB + cc]) = hi;
            *reinterpret_cast<uint32_t*>(&Cl[r * EMB + cc]) = lo;
        }
    }
}

// ---------------------------------------------------------------------------
extern "C" void kernel_launch(void* const* d_in, const int* in_sizes, int n_in,
                              void* d_out, int out_size)
{
    const float* hs   = (const float*)d_in[0];
    const float* kv   = (const float*)d_in[1];
    const float* mask = (const float*)d_in[2];
    const float* hm   = (const float*)d_in[3];
    const float* Wq   = (const float*)d_in[4];
    const float* bq   = (const float*)d_in[5];
    const float* Wk   = (const float*)d_in[6];
    const float* bk   = (const float*)d_in[7];
    const float* Wv   = (const float*)d_in[8];
    const float* bv   = (const float*)d_in[9];
    const float* Wo   = (const float*)d_in[10];
    const float* bo   = (const float*)d_in[11];
    float* out = (float*)d_out;

    __nv_bfloat16 *HSh, *HSl, *KVh, *KVl;
    __nv_bfloat16 *Qh, *Ql, *Kh, *Kl, *Vh, *Vl, *Vth, *Vtl, *Ch, *Cl;
    __nv_bfloat16 *Wqh, *Wql, *Wkh, *Wkl, *Wvh, *Wvl, *Woh, *Wol;
    cudaGetSymbolAddress((void**)&HSh, g_HShi); cudaGetSymbolAddress((void**)&HSl, g_HSlo);
    cudaGetSymbolAddress((void**)&KVh, g_KVhi); cudaGetSymbolAddress((void**)&KVl, g_KVlo);
    cudaGetSymbolAddress((void**)&Qh, g_Qhi);  cudaGetSymbolAddress((void**)&Ql, g_Qlo);
    cudaGetSymbolAddress((void**)&Kh, g_Khi);  cudaGetSymbolAddress((void**)&Kl, g_Klo);
    cudaGetSymbolAddress((void**)&Vh, g_Vhi);  cudaGetSymbolAddress((void**)&Vl, g_Vlo);
    cudaGetSymbolAddress((void**)&Vth, g_Vthi); cudaGetSymbolAddress((void**)&Vtl, g_Vtlo);
    cudaGetSymbolAddress((void**)&Ch, g_Chi);  cudaGetSymbolAddress((void**)&Cl, g_Clo);
    cudaGetSymbolAddress((void**)&Wqh, g_Wqthi); cudaGetSymbolAddress((void**)&Wql, g_Wqtlo);
    cudaGetSymbolAddress((void**)&Wkh, g_Wkthi); cudaGetSymbolAddress((void**)&Wkl, g_Wktlo);
    cudaGetSymbolAddress((void**)&Wvh, g_Wvthi); cudaGetSymbolAddress((void**)&Wvl, g_Wvtlo);
    cudaGetSymbolAddress((void**)&Woh, g_Wothi); cudaGetSymbolAddress((void**)&Wol, g_Wotlo);

    cudaFuncSetAttribute(proj_nt<true>,  cudaFuncAttributeMaxDynamicSharedMemorySize, PROJ_SMEM);
    cudaFuncSetAttribute(proj_nt<false>, cudaFuncAttributeMaxDynamicSharedMemorySize, PROJ_SMEM);
    cudaFuncSetAttribute(flash_attn, cudaFuncAttributeMaxDynamicSharedMemorySize, FLASH_SMEM);

    // Split activations fp32 -> bf16 hi/lo
    split_act<<<(B * T * QIN / 4 + 255) / 256, 256>>>(hs, HSh, HSl, B * T * QIN / 4);
    split_act<<<(B * S * KVIN / 4 + 255) / 256, 256>>>(kv, KVh, KVl, B * S * KVIN / 4);

    // Weight transpose + split
    wsplit_t<<<dim3(EMB / 32, QIN / 32), 256>>>(Wq, QIN, EMB, Wqh, Wql);
    wsplit_t<<<dim3(EMB / 32, KVIN / 32), 256>>>(Wk, KVIN, EMB, Wkh, Wkl);
    wsplit_t<<<dim3(EMB / 32, KVIN / 32), 256>>>(Wv, KVIN, EMB, Wvh, Wvl);
    wsplit_t<<<dim3(EMB / 32, EMB / 32), 256>>>(Wo, EMB, EMB, Woh, Wol);

    // Projections -> split bf16 (Q pre-scaled by SCALING * log2e for exp2 softmax)
    proj_nt<true><<<dim3(EMB / 128, (B * T) / 128), 256, PROJ_SMEM>>>(
        QIN, HSh, HSl, QIN, Wqh, Wql, nullptr, Qh, Ql, EMB, bq, SCALING * LOG2E);
    proj_nt<true><<<dim3(EMB / 128, (B * S) / 128), 256, PROJ_SMEM>>>(
        KVIN, KVh, KVl, KVIN, Wkh, Wkl, nullptr, Kh, Kl, EMB, bk, 1.0f);
    proj_nt<true><<<dim3(EMB / 128, (B * S) / 128), 256, PROJ_SMEM>>>(
        KVIN, KVh, KVl, KVIN, Wvh, Wvl, nullptr, Vh, Vl, EMB, bv, 1.0f);

    // V transpose per head
    vtrans<<<dim3(S / 64, 1, B * H), 256>>>(Vh, Vl, Vth, Vtl);

    // Fused scores + softmax + PV
    flash_attn<<<dim3(T / 128, B * H), 256, FLASH_SMEM>>>(
        Qh, Ql, Kh, Kl, Vth, Vtl, mask, hm, Ch, Cl);

    // out = ctx @ Wo + bo
    proj_nt<false><<<dim3(EMB / 128, (B * T) / 128), 256, PROJ_SMEM>>>(
        EMB, Ch, Cl, EMB, Woh, Wol, out, nullptr, nullptr, EMB, bo, 1.0f);
}

// round 13
// speedup vs baseline: 1.1300x; 1.1252x over previous
#include <cuda_runtime.h>
#include <cuda_bf16.h>
#include <cstdint>

// Problem constants
static constexpr int B   = 8;
static constexpr int T   = 1024;
static constexpr int S   = 1024;
static constexpr int H   = 16;
static constexpr int D   = 64;
static constexpr int EMB = 1024;
static constexpr int QIN = 1024;
static constexpr int KVIN = 256;
static constexpr float SCALING = 0.125f;
static constexpr float LOG2E = 1.4426950408889634f;

// ---------------------------------------------------------------------------
// Scratch (__device__ globals; allocation-free rule)
// ---------------------------------------------------------------------------
__device__ __nv_bfloat16 g_HShi[B * T * QIN],  g_HSlo[B * T * QIN];      // split hs
__device__ __nv_bfloat16 g_KVhi[B * S * KVIN], g_KVlo[B * S * KVIN];     // split kv

__device__ __nv_bfloat16 g_Qhi[B * T * EMB], g_Qlo[B * T * EMB];
__device__ __nv_bfloat16 g_Khi[B * S * EMB], g_Klo[B * S * EMB];
__device__ __nv_bfloat16 g_Vhi[B * S * EMB], g_Vlo[B * S * EMB];
__device__ __nv_bfloat16 g_Vthi[B * H * D * S], g_Vtlo[B * H * D * S];   // [z*D+d][S]
__device__ __nv_bfloat16 g_Chi[B * T * EMB], g_Clo[B * T * EMB];         // ctx

__device__ __nv_bfloat16 g_Wqthi[EMB * QIN],  g_Wqtlo[EMB * QIN];        // [N][K]
__device__ __nv_bfloat16 g_Wkthi[EMB * KVIN], g_Wktlo[EMB * KVIN];
__device__ __nv_bfloat16 g_Wvthi[EMB * KVIN], g_Wvtlo[EMB * KVIN];
__device__ __nv_bfloat16 g_Wothi[EMB * EMB],  g_Wotlo[EMB * EMB];

// ---------------------------------------------------------------------------
// Low-level helpers
// ---------------------------------------------------------------------------
static constexpr int LDSS = 40;   // smem row stride (bf16) for 32-col proj tiles

__device__ __forceinline__ uint32_t ld32(const __nv_bfloat16* p) {
    return *reinterpret_cast<const uint32_t*>(p);
}
__device__ __forceinline__ uint32_t s2u(const void* p) {
    return (uint32_t)__cvta_generic_to_shared(p);
}
__device__ __forceinline__ void cpa16(uint32_t dst, const void* src) {
    asm volatile("cp.async.cg.shared.global [%0], [%1], 16;\n" :: "r"(dst), "l"(src));
}
__device__ __forceinline__ void cpcommit() {
    asm volatile("cp.async.commit_group;\n");
}
template <int N> __device__ __forceinline__ void cpwait() {
    asm volatile("cp.async.wait_group %0;\n" :: "n"(N));
}
__device__ __forceinline__ void ldsm4(uint32_t* r, uint32_t a) {
    asm volatile("ldmatrix.sync.aligned.m8n8.x4.shared.b16 {%0,%1,%2,%3}, [%4];\n"
                 : "=r"(r[0]), "=r"(r[1]), "=r"(r[2]), "=r"(r[3]) : "r"(a));
}
__device__ __forceinline__ void mma16816(float* c, const uint32_t* a, const uint32_t* b) {
    asm volatile(
        "mma.sync.aligned.m16n8k16.row.col.f32.bf16.bf16.f32 "
        "{%0,%1,%2,%3}, {%4,%5,%6,%7}, {%8,%9}, {%0,%1,%2,%3};\n"
        : "+f"(c[0]), "+f"(c[1]), "+f"(c[2]), "+f"(c[3])
        : "r"(a[0]), "r"(a[1]), "r"(a[2]), "r"(a[3]), "r"(b[0]), "r"(b[1]));
}
__device__ __forceinline__ float ex2(float x) {
    float y;
    asm("ex2.approx.f32 %0, %1;" : "=f"(y) : "f"(x));
    return y;
}
__device__ __forceinline__ void split2(float v0, float v1, uint32_t& hi, uint32_t& lo) {
    __nv_bfloat16 h0 = __float2bfloat16(v0), h1 = __float2bfloat16(v1);
    __nv_bfloat16 l0 = __float2bfloat16(v0 - __bfloat162float(h0));
    __nv_bfloat16 l1 = __float2bfloat16(v1 - __bfloat162float(h1));
    __nv_bfloat162 hp; hp.x = h0; hp.y = h1;
    __nv_bfloat162 lp; lp.x = l0; lp.y = l1;
    hi = *reinterpret_cast<uint32_t*>(&hp);
    lo = *reinterpret_cast<uint32_t*>(&lp);
}

// ---------------------------------------------------------------------------
// Activation split: fp32 -> bf16 hi/lo (elementwise, vectorized)
// ---------------------------------------------------------------------------
__global__ __launch_bounds__(256)
void split_act(const float* __restrict__ x,
               __nv_bfloat16* __restrict__ xh, __nv_bfloat16* __restrict__ xl, int n4)
{
    int i = blockIdx.x * 256 + threadIdx.x;
    if (i >= n4) return;
    float4 v = reinterpret_cast<const float4*>(x)[i];
    float vv[4] = {v.x, v.y, v.z, v.w};
    __align__(8) __nv_bfloat16 h[4], l[4];
    #pragma unroll
    for (int j = 0; j < 4; j++) {
        h[j] = __float2bfloat16(vv[j]);
        l[j] = __float2bfloat16(vv[j] - __bfloat162float(h[j]));
    }
    reinterpret_cast<uint2*>(xh)[i] = *reinterpret_cast<uint2*>(h);
    reinterpret_cast<uint2*>(xl)[i] = *reinterpret_cast<uint2*>(l);
}

// ---------------------------------------------------------------------------
// Weight transpose + split: W [K,N] fp32 -> Wt_hi/lo [N,K] bf16
// ---------------------------------------------------------------------------
__global__ __launch_bounds__(256)
void wsplit_t(const float* __restrict__ W, int K, int N,
              __nv_bfloat16* __restrict__ Whi, __nv_bfloat16* __restrict__ Wlo)
{
    __shared__ float sm[32][33];
    const int k0 = blockIdx.y * 32, n0 = blockIdx.x * 32;
    const int tid = threadIdx.x;

    for (int i = tid; i < 32 * 8; i += 256) {
        int r = i >> 3, c4 = i & 7;
        float4 v = *reinterpret_cast<const float4*>(&W[(size_t)(k0 + r) * N + n0 + c4 * 4]);
        sm[r][c4 * 4 + 0] = v.x; sm[r][c4 * 4 + 1] = v.y;
        sm[r][c4 * 4 + 2] = v.z; sm[r][c4 * 4 + 3] = v.w;
    }
    __syncthreads();
    for (int i = tid; i < 32 * 8; i += 256) {
        int n = i >> 3, k4 = i & 7;
        __align__(8) __nv_bfloat16 h[4], l[4];
        #pragma unroll
        for (int j = 0; j < 4; j++) {
            float v = sm[k4 * 4 + j][n];
            h[j] = __float2bfloat16(v);
            l[j] = __float2bfloat16(v - __bfloat162float(h[j]));
        }
        *reinterpret_cast<uint2*>(&Whi[(size_t)(n0 + n) * K + k0 + k4 * 4]) = *reinterpret_cast<uint2*>(h);
        *reinterpret_cast<uint2*>(&Wlo[(size_t)(n0 + n) * K + k0 + k4 * 4]) = *reinterpret_cast<uint2*>(l);
    }
}

// ---------------------------------------------------------------------------
// V transpose (bf16): V [b*S+s][h*D+d] -> Vt [(b*H+h)*D+d][s]
// ---------------------------------------------------------------------------
__global__ __launch_bounds__(256)
void vtrans(const __nv_bfloat16* __restrict__ Vh, const __nv_bfloat16* __restrict__ Vl,
            __nv_bfloat16* __restrict__ Vth, __nv_bfloat16* __restrict__ Vtl)
{
    __shared__ __nv_bfloat16 sm[64][72];
    const int z = blockIdx.z, bb = z >> 4, hh = z & 15;
    const int s0 = blockIdx.x * 64;

    #pragma unroll
    for (int p = 0; p < 2; p++) {
        const __nv_bfloat16* src = p ? Vl : Vh;
        __nv_bfloat16* dst = p ? Vtl : Vth;
        const __nv_bfloat16* sp = src + (size_t)(bb * S + s0) * EMB + hh * D;
        for (int i = threadIdx.x; i < 64 * 16; i += 256) {
            int s = i >> 4, d4 = i & 15;
            *reinterpret_cast<uint2*>(&sm[s][d4 * 4]) =
                *reinterpret_cast<const uint2*>(&sp[(size_t)s * EMB + d4 * 4]);
        }
        __syncthreads();
        __nv_bfloat16* dp = dst + (size_t)z * D * S + s0;
        for (int i = threadIdx.x; i < 64 * 16; i += 256) {
            int d = i >> 4, s4 = i & 15;
            __align__(8) __nv_bfloat16 t[4];
            t[0] = sm[s4 * 4 + 0][d]; t[1] = sm[s4 * 4 + 1][d];
            t[2] = sm[s4 * 4 + 2][d]; t[3] = sm[s4 * 4 + 3][d];
            *reinterpret_cast<uint2*>(&dp[(size_t)d * S + s4 * 4]) = *reinterpret_cast<uint2*>(t);
        }
        __syncthreads();
    }
}

// ---------------------------------------------------------------------------
// Projection GEMM (NT), split-bf16 3-MMA, 2-stage cp.async pipeline + ldmatrix.
// (R8 structure: 81920 B smem -> 2 CTAs/SM.)
// ---------------------------------------------------------------------------
static constexpr int PTILE = 128 * LDSS;
static constexpr int PROJ_SMEM = 2 * 4 * PTILE * (int)sizeof(__nv_bfloat16);  // 81920

template <bool OUT_SPLIT>
__global__ __launch_bounds__(256)
void proj_nt(int K,
             const __nv_bfloat16* __restrict__ Ah, const __nv_bfloat16* __restrict__ Al,
             int lda,
             const __nv_bfloat16* __restrict__ Bth, const __nv_bfloat16* __restrict__ Btl,
             float* __restrict__ Cf,
             __nv_bfloat16* __restrict__ Ch, __nv_bfloat16* __restrict__ Cl,
             int ldc, const float* __restrict__ bias, float alpha)
{
    extern __shared__ __nv_bfloat16 smp[];   // [2][4][PTILE]

    const int tid = threadIdx.x, lane = tid & 31, wid = tid >> 5;
    const int wm = wid >> 2, wn = wid & 3;
    const int row0 = blockIdx.y * 128, col0 = blockIdx.x * 128;

    const __nv_bfloat16* aH = Ah + (size_t)row0 * lda;
    const __nv_bfloat16* aL = Al + (size_t)row0 * lda;
    const __nv_bfloat16* bH = Bth + (size_t)col0 * K;
    const __nv_bfloat16* bL = Btl + (size_t)col0 * K;

    const int g = lane >> 3, li = lane & 7;
    const int ar = ((g & 1) * 8) + li, ac = (g >> 1) * 8;   // A-frag ldmatrix lane map
    const int br = ((g >> 1) * 8) + li, bc = (g & 1) * 8;   // B-frag ldmatrix lane map

    float acc[4][4][4] = {};

    auto stage = [&](int st, int k0) {
        __nv_bfloat16* d = smp + st * 4 * PTILE;
        #pragma unroll
        for (int i = tid; i < 512; i += 256) {
            int r = i >> 2, c = (i & 3) * 8;
            cpa16(s2u(d + 0 * PTILE + r * LDSS + c), aH + (size_t)r * lda + k0 + c);
            cpa16(s2u(d + 1 * PTILE + r * LDSS + c), aL + (size_t)r * lda + k0 + c);
            cpa16(s2u(d + 2 * PTILE + r * LDSS + c), bH + (size_t)r * K + k0 + c);
            cpa16(s2u(d + 3 * PTILE + r * LDSS + c), bL + (size_t)r * K + k0 + c);
        }
    };

    auto compute = [&](int st) {
        const __nv_bfloat16* Ash = smp + st * 4 * PTILE;
        const __nv_bfloat16* Asl = Ash + PTILE;
        const __nv_bfloat16* Bsh = Asl + PTILE;
        const __nv_bfloat16* Bsl = Bsh + PTILE;
        #pragma unroll
        for (int ks = 0; ks < 2; ks++) {
            const int c = ks * 16;
            uint32_t ah[4][4], al[4][4], bh[2][4], bl[2][4];
            #pragma unroll
            for (int mt = 0; mt < 4; mt++) {
                int r = wm * 64 + mt * 16 + ar;
                ldsm4(ah[mt], s2u(Ash + r * LDSS + c + ac));
                ldsm4(al[mt], s2u(Asl + r * LDSS + c + ac));
            }
            #pragma unroll
            for (int np = 0; np < 2; np++) {
                int n = wn * 32 + np * 16 + br;
                ldsm4(bh[np], s2u(Bsh + n * LDSS + c + bc));
                ldsm4(bl[np], s2u(Bsl + n * LDSS + c + bc));
            }
            #pragma unroll
            for (int mt = 0; mt < 4; mt++)
                #pragma unroll
                for (int nt = 0; nt < 4; nt++) {
                    const uint32_t* bph = &bh[nt >> 1][(nt & 1) * 2];
                    const uint32_t* bpl = &bl[nt >> 1][(nt & 1) * 2];
                    mma16816(acc[mt][nt], ah[mt], bph);
                    mma16816(acc[mt][nt], ah[mt], bpl);
                    mma16816(acc[mt][nt], al[mt], bph);
                }
        }
    };

    const int nit = K / 32;
    stage(0, 0);
    cpcommit();
    for (int it = 0; it < nit; it++) {
        if (it + 1 < nit) { stage((it + 1) & 1, (it + 1) * 32); cpcommit(); }
        if (it + 1 < nit) cpwait<1>(); else cpwait<0>();
        __syncthreads();
        compute(it & 1);
        __syncthreads();
    }

    #pragma unroll
    for (int mt = 0; mt < 4; mt++)
        #pragma unroll
        for (int nt = 0; nt < 4; nt++) {
            int r0 = row0 + wm * 64 + mt * 16 + (lane >> 2);
            int cc = col0 + wn * 32 + nt * 8 + ((lane & 3) << 1);
            float b0 = bias[cc], b1 = bias[cc + 1];
            #pragma unroll
            for (int half = 0; half < 2; half++) {
                int r = r0 + half * 8;
                float v0 = (acc[mt][nt][half * 2 + 0] + b0) * alpha;
                float v1 = (acc[mt][nt][half * 2 + 1] + b1) * alpha;
                if (OUT_SPLIT) {
                    uint32_t hi, lo;
                    split2(v0, v1, hi, lo);
                    *reinterpret_cast<uint32_t*>(&Ch[(size_t)r * ldc + cc]) = hi;
                    *reinterpret_cast<uint32_t*>(&Cl[(size_t)r * ldc + cc]) = lo;
                } else {
                    float2 o; o.x = v0; o.y = v1;
                    *reinterpret_cast<float2*>(&Cf[(size_t)r * ldc + cc]) = o;
                }
            }
        }
}

// ---------------------------------------------------------------------------
// Fused flash attention. s-tile = 64 (halved) -> stage 36 KB, 2 stages,
// 2 CTAs/SM for tensor/softmax overlap across CTAs. exp2-domain softmax,
// 3-term split PV (accuracy-safe). Grid: (T/128, B*H), 256 threads / 8 warps.
// ---------------------------------------------------------------------------
static constexpr int STILE = 64;
static constexpr int LDK = 72;    // K tile [64 s][64 k] row stride
static constexpr int LDV = 72;    // V tile [64 d][64 s] row stride
static constexpr int KTILE = STILE * LDK;
static constexpr int VTILE = 64 * LDV;
static constexpr int FSTAGE = 2 * KTILE + 2 * VTILE;   // 18432 elems = 36 KB
static constexpr int FLASH_SMEM = 2 * FSTAGE * (int)sizeof(__nv_bfloat16);  // 73728

__global__ __launch_bounds__(256, 2)
void flash_attn(const __nv_bfloat16* __restrict__ Qh, const __nv_bfloat16* __restrict__ Ql,
                const __nv_bfloat16* __restrict__ Kh, const __nv_bfloat16* __restrict__ Kl,
                const __nv_bfloat16* __restrict__ Vth, const __nv_bfloat16* __restrict__ Vtl,
                const float* __restrict__ mask, const float* __restrict__ head_mask,
                __nv_bfloat16* __restrict__ Ch, __nv_bfloat16* __restrict__ Cl)
{
    extern __shared__ __nv_bfloat16 smf[];   // [2][FSTAGE]

    const int tid = threadIdx.x, lane = tid & 31, wid = tid >> 5;
    const int z = blockIdx.y, bb = z >> 4, hh = z & 15;
    const int row0 = blockIdx.x * 128;
    const int tr = row0 + wid * 16 + (lane >> 2);

    const int g = lane >> 3, li = lane & 7;
    const int br = ((g >> 1) * 8) + li, bc = (g & 1) * 8;

    // ---- Q fragments (register-resident), k = 0..63; already log2e-scaled ----
    uint32_t qfh[4][4], qfl[4][4];
    {
        const size_t qrow = (size_t)(bb * T + tr) * EMB + hh * D;
        #pragma unroll
        for (int ks = 0; ks < 4; ks++) {
            const int c = ks * 16 + (lane & 3) * 2;
            qfh[ks][0] = ld32(Qh + qrow + c);
            qfh[ks][1] = ld32(Qh + qrow + (size_t)8 * EMB + c);
            qfh[ks][2] = ld32(Qh + qrow + c + 8);
            qfh[ks][3] = ld32(Qh + qrow + (size_t)8 * EMB + c + 8);
            qfl[ks][0] = ld32(Ql + qrow + c);
            qfl[ks][1] = ld32(Ql + qrow + (size_t)8 * EMB + c);
            qfl[ks][2] = ld32(Ql + qrow + c + 8);
            qfl[ks][3] = ld32(Ql + qrow + (size_t)8 * EMB + c + 8);
        }
    }

    float oacc[8][4] = {};
    float mrun[2] = {-1e30f, -1e30f};
    float lrun[2] = {0.0f, 0.0f};

    const __nv_bfloat16* kbase_h = Kh + (size_t)bb * S * EMB + hh * D;
    const __nv_bfloat16* kbase_l = Kl + (size_t)bb * S * EMB + hh * D;
    const __nv_bfloat16* vbase_h = Vth + (size_t)z * D * S;
    const __nv_bfloat16* vbase_l = Vtl + (size_t)z * D * S;
    const float* Mz = mask + (size_t)bb * T * S;

    auto stageKV = [&](int st, int s0) {
        __nv_bfloat16* kd  = smf + st * FSTAGE;
        __nv_bfloat16* kdl = kd + KTILE;
        __nv_bfloat16* vd  = kdl + KTILE;
        __nv_bfloat16* vdl = vd + VTILE;
        #pragma unroll
        for (int i = tid; i < 512; i += 256) {
            int r = i >> 3, c = (i & 7) * 8;
            cpa16(s2u(kd  + r * LDK + c), kbase_h + (size_t)(s0 + r) * EMB + c);
            cpa16(s2u(kdl + r * LDK + c), kbase_l + (size_t)(s0 + r) * EMB + c);
        }
        #pragma unroll
        for (int i = tid; i < 512; i += 256) {
            int r = i >> 3, c = (i & 7) * 8;
            cpa16(s2u(vd  + r * LDV + c), vbase_h + (size_t)r * S + s0 + c);
            cpa16(s2u(vdl + r * LDV + c), vbase_l + (size_t)r * S + s0 + c);
        }
    };

    stageKV(0, 0);
    cpcommit();

    constexpr int NS = S / STILE;   // 16
    for (int is = 0; is < NS; is++) {
        if (is + 1 < NS) { stageKV((is + 1) & 1, (is + 1) * STILE); cpcommit(); }
        if (is + 1 < NS) cpwait<1>(); else cpwait<0>();
        __syncthreads();

        const int s0 = is * STILE;
        const __nv_bfloat16* Ksh = smf + (is & 1) * FSTAGE;
        const __nv_bfloat16* Ksl = Ksh + KTILE;
        const __nv_bfloat16* Vsh = Ksl + KTILE;
        const __nv_bfloat16* Vsl = Vsh + VTILE;

        // ---- scores (log2 domain): 16(t) x 64(s) per warp ----
        float sacc[8][4] = {};
        #pragma unroll
        for (int ks = 0; ks < 4; ks++) {
            const int c = ks * 16;
            #pragma unroll
            for (int np = 0; np < 4; np++) {
                const int n = np * 16 + br;
                uint32_t kbh[4], kbl[4];
                ldsm4(kbh, s2u(Ksh + n * LDK + c + bc));
                ldsm4(kbl, s2u(Ksl + n * LDK + c + bc));
                mma16816(sacc[2 * np],     qfh[ks], kbh);
                mma16816(sacc[2 * np],     qfh[ks], kbl);
                mma16816(sacc[2 * np],     qfl[ks], kbh);
                mma16816(sacc[2 * np + 1], qfh[ks], kbh + 2);
                mma16816(sacc[2 * np + 1], qfh[ks], kbl + 2);
                mma16816(sacc[2 * np + 1], qfl[ks], kbh + 2);
            }
        }

        // ---- + mask * log2e (FFMA) ----
        #pragma unroll
        for (int nt = 0; nt < 8; nt++) {
            const int cg = s0 + nt * 8 + (lane & 3) * 2;
            float2 m0 = *reinterpret_cast<const float2*>(&Mz[(size_t)tr * S + cg]);
            float2 m1 = *reinterpret_cast<const float2*>(&Mz[(size_t)(tr + 8) * S + cg]);
            sacc[nt][0] = fmaf(m0.x, LOG2E, sacc[nt][0]);
            sacc[nt][1] = fmaf(m0.y, LOG2E, sacc[nt][1]);
            sacc[nt][2] = fmaf(m1.x, LOG2E, sacc[nt][2]);
            sacc[nt][3] = fmaf(m1.y, LOG2E, sacc[nt][3]);
        }

        // ---- online softmax in exp2 domain (per row-half) ----
        #pragma unroll
        for (int hf = 0; hf < 2; hf++) {
            float vm = -1e30f;
            #pragma unroll
            for (int nt = 0; nt < 8; nt++)
                vm = fmaxf(vm, fmaxf(sacc[nt][hf * 2], sacc[nt][hf * 2 + 1]));
            vm = fmaxf(vm, __shfl_xor_sync(0xffffffffu, vm, 1));
            vm = fmaxf(vm, __shfl_xor_sync(0xffffffffu, vm, 2));
            const float mnew = fmaxf(mrun[hf], vm);
            const float f = ex2(mrun[hf] - mnew);
            mrun[hf] = mnew;
            lrun[hf] *= f;
            #pragma unroll
            for (int nt = 0; nt < 8; nt++) {
                oacc[nt][hf * 2 + 0] *= f;
                oacc[nt][hf * 2 + 1] *= f;
            }
            float ls = 0.0f;
            #pragma unroll
            for (int nt = 0; nt < 8; nt++) {
                float e0 = ex2(sacc[nt][hf * 2 + 0] - mnew);
                float e1 = ex2(sacc[nt][hf * 2 + 1] - mnew);
                sacc[nt][hf * 2 + 0] = e0;
                sacc[nt][hf * 2 + 1] = e1;
                ls += e0 + e1;
            }
            lrun[hf] += ls;
        }

        // ---- PV: O(16t x 64d) += P(16t x 64s) @ Vt(64d x 64s)^T, 3-term ----
        #pragma unroll
        for (int ks = 0; ks < 4; ks++) {
            uint32_t ph[4], pl[4];
            split2(sacc[2 * ks][0],     sacc[2 * ks][1],     ph[0], pl[0]);
            split2(sacc[2 * ks][2],     sacc[2 * ks][3],     ph[1], pl[1]);
            split2(sacc[2 * ks + 1][0], sacc[2 * ks + 1][1], ph[2], pl[2]);
            split2(sacc[2 * ks + 1][2], sacc[2 * ks + 1][3], ph[3], pl[3]);
            const int c = ks * 16;
            #pragma unroll
            for (int np = 0; np < 4; np++) {
                const int n = np * 16 + br;
                uint32_t vbh[4], vbl[4];
                ldsm4(vbh, s2u(Vsh + n * LDV + c + bc));
                ldsm4(vbl, s2u(Vsl + n * LDV + c + bc));
                mma16816(oacc[2 * np],     ph, vbh);
                mma16816(oacc[2 * np],     ph, vbl);
                mma16816(oacc[2 * np],     pl, vbh);
                mma16816(oacc[2 * np + 1], ph, vbh + 2);
                mma16816(oacc[2 * np + 1], ph, vbl + 2);
                mma16816(oacc[2 * np + 1], pl, vbh + 2);
            }
        }
        __syncthreads();
    }

    // ---- epilogue: normalize, head-mask scale, split to ctx hi/lo ----
    float scale[2];
    #pragma unroll
    for (int hf = 0; hf < 2; hf++) {
        float l = lrun[hf];
        l += __shfl_xor_sync(0xffffffffu, l, 1);
        l += __shfl_xor_sync(0xffffffffu, l, 2);
        scale[hf] = head_mask[hh] / l;
    }
    #pragma unroll
    for (int nt = 0; nt < 8; nt++) {
        const int cc = hh * D + nt * 8 + (lane & 3) * 2;
        #pragma unroll
        for (int hf = 0; hf < 2; hf++) {
            const size_t r = (size_t)(bb * T + tr + hf * 8);
            uint32_t hi, lo;
            split2(oacc[nt][hf * 2 + 0] * scale[hf],
                   oacc[nt][hf * 2 + 1] * scale[hf], hi, lo);
            *reinterpret_cast<uint32_t*>(&Ch[r * EMB + cc]) = hi;
            *reinterpret_cast<uint32_t*>(&Cl[r * EMB + cc]) = lo;
        }
    }
}

// ---------------------------------------------------------------------------
extern "C" void kernel_launch(void* const* d_in, const int* in_sizes, int n_in,
                              void* d_out, int out_size)
{
    const float* hs   = (const float*)d_in[0];
    const float* kv   = (const float*)d_in[1];
    const float* mask = (const float*)d_in[2];
    const float* hm   = (const float*)d_in[3];
    const float* Wq   = (const float*)d_in[4];
    const float* bq   = (const float*)d_in[5];
    const float* Wk   = (const float*)d_in[6];
    const float* bk   = (const float*)d_in[7];
    const float* Wv   = (const float*)d_in[8];
    const float* bv   = (const float*)d_in[9];
    const float* Wo   = (const float*)d_in[10];
    const float* bo   = (const float*)d_in[11];
    float* out = (float*)d_out;

    __nv_bfloat16 *HSh, *HSl, *KVh, *KVl;
    __nv_bfloat16 *Qh, *Ql, *Kh, *Kl, *Vh, *Vl, *Vth, *Vtl, *Ch, *Cl;
    __nv_bfloat16 *Wqh, *Wql, *Wkh, *Wkl, *Wvh, *Wvl, *Woh, *Wol;
    cudaGetSymbolAddress((void**)&HSh, g_HShi); cudaGetSymbolAddress((void**)&HSl, g_HSlo);
    cudaGetSymbolAddress((void**)&KVh, g_KVhi); cudaGetSymbolAddress((void**)&KVl, g_KVlo);
    cudaGetSymbolAddress((void**)&Qh, g_Qhi);  cudaGetSymbolAddress((void**)&Ql, g_Qlo);
    cudaGetSymbolAddress((void**)&Kh, g_Khi);  cudaGetSymbolAddress((void**)&Kl, g_Klo);
    cudaGetSymbolAddress((void**)&Vh, g_Vhi);  cudaGetSymbolAddress((void**)&Vl, g_Vlo);
    cudaGetSymbolAddress((void**)&Vth, g_Vthi); cudaGetSymbolAddress((void**)&Vtl, g_Vtlo);
    cudaGetSymbolAddress((void**)&Ch, g_Chi);  cudaGetSymbolAddress((void**)&Cl, g_Clo);
    cudaGetSymbolAddress((void**)&Wqh, g_Wqthi); cudaGetSymbolAddress((void**)&Wql, g_Wqtlo);
    cudaGetSymbolAddress((void**)&Wkh, g_Wkthi); cudaGetSymbolAddress((void**)&Wkl, g_Wktlo);
    cudaGetSymbolAddress((void**)&Wvh, g_Wvthi); cudaGetSymbolAddress((void**)&Wvl, g_Wvtlo);
    cudaGetSymbolAddress((void**)&Woh, g_Wothi); cudaGetSymbolAddress((void**)&Wol, g_Wotlo);

    cudaFuncSetAttribute(proj_nt<true>,  cudaFuncAttributeMaxDynamicSharedMemorySize, PROJ_SMEM);
    cudaFuncSetAttribute(proj_nt<false>, cudaFuncAttributeMaxDynamicSharedMemorySize, PROJ_SMEM);
    cudaFuncSetAttribute(flash_attn, cudaFuncAttributeMaxDynamicSharedMemorySize, FLASH_SMEM);

    // Split activations fp32 -> bf16 hi/lo
    split_act<<<(B * T * QIN / 4 + 255) / 256, 256>>>(hs, HSh, HSl, B * T * QIN / 4);
    split_act<<<(B * S * KVIN / 4 + 255) / 256, 256>>>(kv, KVh, KVl, B * S * KVIN / 4);

    // Weight transpose + split
    wsplit_t<<<dim3(EMB / 32, QIN / 32), 256>>>(Wq, QIN, EMB, Wqh, Wql);
    wsplit_t<<<dim3(EMB / 32, KVIN / 32), 256>>>(Wk, KVIN, EMB, Wkh, Wkl);
    wsplit_t<<<dim3(EMB / 32, KVIN / 32), 256>>>(Wv, KVIN, EMB, Wvh, Wvl);
    wsplit_t<<<dim3(EMB / 32, EMB / 32), 256>>>(Wo, EMB, EMB, Woh, Wol);

    // Projections -> split bf16 (Q pre-scaled by SCALING * log2e for exp2 softmax)
    proj_nt<true><<<dim3(EMB / 128, (B * T) / 128), 256, PROJ_SMEM>>>(
        QIN, HSh, HSl, QIN, Wqh, Wql, nullptr, Qh, Ql, EMB, bq, SCALING * LOG2E);
    proj_nt<true><<<dim3(EMB / 128, (B * S) / 128), 256, PROJ_SMEM>>>(
        KVIN, KVh, KVl, KVIN, Wkh, Wkl, nullptr, Kh, Kl, EMB, bk, 1.0f);
    proj_nt<true><<<dim3(EMB / 128, (B * S) / 128), 256, PROJ_SMEM>>>(
        KVIN, KVh, KVl, KVIN, Wvh, Wvl, nullptr, Vh, Vl, EMB, bv, 1.0f);

    // V transpose per head
    vtrans<<<dim3(S / 64, 1, B * H), 256>>>(Vh, Vl, Vth, Vtl);

    // Fused scores + softmax + PV
    flash_attn<<<dim3(T / 128, B * H), 256, FLASH_SMEM>>>(
        Qh, Ql, Kh, Kl, Vth, Vtl, mask, hm, Ch, Cl);

    // out = ctx @ Wo + bo
    proj_nt<false><<<dim3(EMB / 128, (B * T) / 128), 256, PROJ_SMEM>>>(
        EMB, Ch, Cl, EMB, Woh, Wol, out, nullptr, nullptr, EMB, bo, 1.0f);
}

// round 14
// speedup vs baseline: 1.2551x; 1.1107x over previous
#include <cuda_runtime.h>
#include <cuda_bf16.h>
#include <cuda_fp16.h>
#include <cstdint>

// Problem constants
static constexpr int B   = 8;
static constexpr int T   = 1024;
static constexpr int S   = 1024;
static constexpr int H   = 16;
static constexpr int D   = 64;
static constexpr int EMB = 1024;
static constexpr int QIN = 1024;
static constexpr int KVIN = 256;
static constexpr float SCALING = 0.125f;
static constexpr float LOG2E = 1.4426950408889634f;

// ---------------------------------------------------------------------------
// Scratch (__device__ globals; allocation-free rule)
// ---------------------------------------------------------------------------
__device__ __nv_bfloat16 g_HShi[B * T * QIN],  g_HSlo[B * T * QIN];      // split hs
__device__ __nv_bfloat16 g_KVhi[B * S * KVIN], g_KVlo[B * S * KVIN];     // split kv

__device__ __nv_bfloat16 g_Qhi[B * T * EMB], g_Qlo[B * T * EMB];
__device__ __nv_bfloat16 g_Khi[B * S * EMB], g_Klo[B * S * EMB];
__device__ __nv_bfloat16 g_Vhi[B * S * EMB], g_Vlo[B * S * EMB];
__device__ __nv_bfloat16 g_Vthi[B * H * D * S], g_Vtlo[B * H * D * S];   // [z*D+d][S]
__device__ __half        g_Cf16[B * T * EMB];                            // ctx (fp16)

__device__ __nv_bfloat16 g_Wqthi[EMB * QIN],  g_Wqtlo[EMB * QIN];        // [N][K]
__device__ __nv_bfloat16 g_Wkthi[EMB * KVIN], g_Wktlo[EMB * KVIN];
__device__ __nv_bfloat16 g_Wvthi[EMB * KVIN], g_Wvtlo[EMB * KVIN];
__device__ __half        g_Wot16h[EMB * EMB], g_Wot16l[EMB * EMB];       // fp16 hi/lo

// ---------------------------------------------------------------------------
// Low-level helpers
// ---------------------------------------------------------------------------
static constexpr int LDSS = 40;   // smem row stride (16-bit elems) for 32-col tiles

__device__ __forceinline__ uint32_t ld32(const __nv_bfloat16* p) {
    return *reinterpret_cast<const uint32_t*>(p);
}
__device__ __forceinline__ uint32_t s2u(const void* p) {
    return (uint32_t)__cvta_generic_to_shared(p);
}
__device__ __forceinline__ void cpa16(uint32_t dst, const void* src) {
    asm volatile("cp.async.cg.shared.global [%0], [%1], 16;\n" :: "r"(dst), "l"(src));
}
__device__ __forceinline__ void cpcommit() {
    asm volatile("cp.async.commit_group;\n");
}
template <int N> __device__ __forceinline__ void cpwait() {
    asm volatile("cp.async.wait_group %0;\n" :: "n"(N));
}
__device__ __forceinline__ void ldsm4(uint32_t* r, uint32_t a) {
    asm volatile("ldmatrix.sync.aligned.m8n8.x4.shared.b16 {%0,%1,%2,%3}, [%4];\n"
                 : "=r"(r[0]), "=r"(r[1]), "=r"(r[2]), "=r"(r[3]) : "r"(a));
}
__device__ __forceinline__ void mma16816(float* c, const uint32_t* a, const uint32_t* b) {
    asm volatile(
        "mma.sync.aligned.m16n8k16.row.col.f32.bf16.bf16.f32 "
        "{%0,%1,%2,%3}, {%4,%5,%6,%7}, {%8,%9}, {%0,%1,%2,%3};\n"
        : "+f"(c[0]), "+f"(c[1]), "+f"(c[2]), "+f"(c[3])
        : "r"(a[0]), "r"(a[1]), "r"(a[2]), "r"(a[3]), "r"(b[0]), "r"(b[1]));
}
__device__ __forceinline__ void mma16816h(float* c, const uint32_t* a, const uint32_t* b) {
    asm volatile(
        "mma.sync.aligned.m16n8k16.row.col.f32.f16.f16.f32 "
        "{%0,%1,%2,%3}, {%4,%5,%6,%7}, {%8,%9}, {%0,%1,%2,%3};\n"
        : "+f"(c[0]), "+f"(c[1]), "+f"(c[2]), "+f"(c[3])
        : "r"(a[0]), "r"(a[1]), "r"(a[2]), "r"(a[3]), "r"(b[0]), "r"(b[1]));
}
__device__ __forceinline__ float ex2(float x) {
    float y;
    asm("ex2.approx.f32 %0, %1;" : "=f"(y) : "f"(x));
    return y;
}
__device__ __forceinline__ void split2(float v0, float v1, uint32_t& hi, uint32_t& lo) {
    __nv_bfloat16 h0 = __float2bfloat16(v0), h1 = __float2bfloat16(v1);
    __nv_bfloat16 l0 = __float2bfloat16(v0 - __bfloat162float(h0));
    __nv_bfloat16 l1 = __float2bfloat16(v1 - __bfloat162float(h1));
    __nv_bfloat162 hp; hp.x = h0; hp.y = h1;
    __nv_bfloat162 lp; lp.x = l0; lp.y = l1;
    hi = *reinterpret_cast<uint32_t*>(&hp);
    lo = *reinterpret_cast<uint32_t*>(&lp);
}

// ---------------------------------------------------------------------------
// Activation split: fp32 -> bf16 hi/lo (elementwise, vectorized)
// ---------------------------------------------------------------------------
__global__ __launch_bounds__(256)
void split_act(const float* __restrict__ x,
               __nv_bfloat16* __restrict__ xh, __nv_bfloat16* __restrict__ xl, int n4)
{
    int i = blockIdx.x * 256 + threadIdx.x;
    if (i >= n4) return;
    float4 v = reinterpret_cast<const float4*>(x)[i];
    float vv[4] = {v.x, v.y, v.z, v.w};
    __align__(8) __nv_bfloat16 h[4], l[4];
    #pragma unroll
    for (int j = 0; j < 4; j++) {
        h[j] = __float2bfloat16(vv[j]);
        l[j] = __float2bfloat16(vv[j] - __bfloat162float(h[j]));
    }
    reinterpret_cast<uint2*>(xh)[i] = *reinterpret_cast<uint2*>(h);
    reinterpret_cast<uint2*>(xl)[i] = *reinterpret_cast<uint2*>(l);
}

// ---------------------------------------------------------------------------
// Weight transpose + split (bf16): W [K,N] fp32 -> Wt_hi/lo [N,K] bf16
// ---------------------------------------------------------------------------
__global__ __launch_bounds__(256)
void wsplit_t(const float* __restrict__ W, int K, int N,
              __nv_bfloat16* __restrict__ Whi, __nv_bfloat16* __restrict__ Wlo)
{
    __shared__ float sm[32][33];
    const int k0 = blockIdx.y * 32, n0 = blockIdx.x * 32;
    const int tid = threadIdx.x;

    for (int i = tid; i < 32 * 8; i += 256) {
        int r = i >> 3, c4 = i & 7;
        float4 v = *reinterpret_cast<const float4*>(&W[(size_t)(k0 + r) * N + n0 + c4 * 4]);
        sm[r][c4 * 4 + 0] = v.x; sm[r][c4 * 4 + 1] = v.y;
        sm[r][c4 * 4 + 2] = v.z; sm[r][c4 * 4 + 3] = v.w;
    }
    __syncthreads();
    for (int i = tid; i < 32 * 8; i += 256) {
        int n = i >> 3, k4 = i & 7;
        __align__(8) __nv_bfloat16 h[4], l[4];
        #pragma unroll
        for (int j = 0; j < 4; j++) {
            float v = sm[k4 * 4 + j][n];
            h[j] = __float2bfloat16(v);
            l[j] = __float2bfloat16(v - __bfloat162float(h[j]));
        }
        *reinterpret_cast<uint2*>(&Whi[(size_t)(n0 + n) * K + k0 + k4 * 4]) = *reinterpret_cast<uint2*>(h);
        *reinterpret_cast<uint2*>(&Wlo[(size_t)(n0 + n) * K + k0 + k4 * 4]) = *reinterpret_cast<uint2*>(l);
    }
}

// ---------------------------------------------------------------------------
// Weight transpose + split (fp16): W [K,N] fp32 -> Wt_hi/lo [N,K] fp16
// ---------------------------------------------------------------------------
__global__ __launch_bounds__(256)
void wsplit_t16(const float* __restrict__ W, int K, int N,
                __half* __restrict__ Whi, __half* __restrict__ Wlo)
{
    __shared__ float sm[32][33];
    const int k0 = blockIdx.y * 32, n0 = blockIdx.x * 32;
    const int tid = threadIdx.x;

    for (int i = tid; i < 32 * 8; i += 256) {
        int r = i >> 3, c4 = i & 7;
        float4 v = *reinterpret_cast<const float4*>(&W[(size_t)(k0 + r) * N + n0 + c4 * 4]);
        sm[r][c4 * 4 + 0] = v.x; sm[r][c4 * 4 + 1] = v.y;
        sm[r][c4 * 4 + 2] = v.z; sm[r][c4 * 4 + 3] = v.w;
    }
    __syncthreads();
    for (int i = tid; i < 32 * 8; i += 256) {
        int n = i >> 3, k4 = i & 7;
        __align__(8) __half h[4], l[4];
        #pragma unroll
        for (int j = 0; j < 4; j++) {
            float v = sm[k4 * 4 + j][n];
            h[j] = __float2half(v);
            l[j] = __float2half(v - __half2float(h[j]));
        }
        *reinterpret_cast<uint2*>(&Whi[(size_t)(n0 + n) * K + k0 + k4 * 4]) = *reinterpret_cast<uint2*>(h);
        *reinterpret_cast<uint2*>(&Wlo[(size_t)(n0 + n) * K + k0 + k4 * 4]) = *reinterpret_cast<uint2*>(l);
    }
}

// ---------------------------------------------------------------------------
// V transpose (bf16): V [b*S+s][h*D+d] -> Vt [(b*H+h)*D+d][s]
// ---------------------------------------------------------------------------
__global__ __launch_bounds__(256)
void vtrans(const __nv_bfloat16* __restrict__ Vh, const __nv_bfloat16* __restrict__ Vl,
            __nv_bfloat16* __restrict__ Vth, __nv_bfloat16* __restrict__ Vtl)
{
    __shared__ __nv_bfloat16 sm[64][72];
    const int z = blockIdx.z, bb = z >> 4, hh = z & 15;
    const int s0 = blockIdx.x * 64;

    #pragma unroll
    for (int p = 0; p < 2; p++) {
        const __nv_bfloat16* src = p ? Vl : Vh;
        __nv_bfloat16* dst = p ? Vtl : Vth;
        const __nv_bfloat16* sp = src + (size_t)(bb * S + s0) * EMB + hh * D;
        for (int i = threadIdx.x; i < 64 * 16; i += 256) {
            int s = i >> 4, d4 = i & 15;
            *reinterpret_cast<uint2*>(&sm[s][d4 * 4]) =
                *reinterpret_cast<const uint2*>(&sp[(size_t)s * EMB + d4 * 4]);
        }
        __syncthreads();
        __nv_bfloat16* dp = dst + (size_t)z * D * S + s0;
        for (int i = threadIdx.x; i < 64 * 16; i += 256) {
            int d = i >> 4, s4 = i & 15;
            __align__(8) __nv_bfloat16 t[4];
            t[0] = sm[s4 * 4 + 0][d]; t[1] = sm[s4 * 4 + 1][d];
            t[2] = sm[s4 * 4 + 2][d]; t[3] = sm[s4 * 4 + 3][d];
            *reinterpret_cast<uint2*>(&dp[(size_t)d * S + s4 * 4]) = *reinterpret_cast<uint2*>(t);
        }
        __syncthreads();
    }
}

// ---------------------------------------------------------------------------
// Projection GEMM (NT), split-bf16 3-MMA, 2-stage cp.async pipeline + ldmatrix.
// (R8/R13 structure: 81920 B smem -> 2 CTAs/SM.)  Outputs split bf16.
// ---------------------------------------------------------------------------
static constexpr int PTILE = 128 * LDSS;
static constexpr int PROJ_SMEM = 2 * 4 * PTILE * (int)sizeof(__nv_bfloat16);  // 81920

__global__ __launch_bounds__(256)
void proj_nt(int K,
             const __nv_bfloat16* __restrict__ Ah, const __nv_bfloat16* __restrict__ Al,
             int lda,
             const __nv_bfloat16* __restrict__ Bth, const __nv_bfloat16* __restrict__ Btl,
             __nv_bfloat16* __restrict__ Ch, __nv_bfloat16* __restrict__ Cl,
             int ldc, const float* __restrict__ bias, float alpha)
{
    extern __shared__ __nv_bfloat16 smp[];   // [2][4][PTILE]

    const int tid = threadIdx.x, lane = tid & 31, wid = tid >> 5;
    const int wm = wid >> 2, wn = wid & 3;
    const int row0 = blockIdx.y * 128, col0 = blockIdx.x * 128;

    const __nv_bfloat16* aH = Ah + (size_t)row0 * lda;
    const __nv_bfloat16* aL = Al + (size_t)row0 * lda;
    const __nv_bfloat16* bH = Bth + (size_t)col0 * K;
    const __nv_bfloat16* bL = Btl + (size_t)col0 * K;

    const int g = lane >> 3, li = lane & 7;
    const int ar = ((g & 1) * 8) + li, ac = (g >> 1) * 8;
    const int br = ((g >> 1) * 8) + li, bc = (g & 1) * 8;

    float acc[4][4][4] = {};

    auto stage = [&](int st, int k0) {
        __nv_bfloat16* d = smp + st * 4 * PTILE;
        #pragma unroll
        for (int i = tid; i < 512; i += 256) {
            int r = i >> 2, c = (i & 3) * 8;
            cpa16(s2u(d + 0 * PTILE + r * LDSS + c), aH + (size_t)r * lda + k0 + c);
            cpa16(s2u(d + 1 * PTILE + r * LDSS + c), aL + (size_t)r * lda + k0 + c);
            cpa16(s2u(d + 2 * PTILE + r * LDSS + c), bH + (size_t)r * K + k0 + c);
            cpa16(s2u(d + 3 * PTILE + r * LDSS + c), bL + (size_t)r * K + k0 + c);
        }
    };

    auto compute = [&](int st) {
        const __nv_bfloat16* Ash = smp + st * 4 * PTILE;
        const __nv_bfloat16* Asl = Ash + PTILE;
        const __nv_bfloat16* Bsh = Asl + PTILE;
        const __nv_bfloat16* Bsl = Bsh + PTILE;
        #pragma unroll
        for (int ks = 0; ks < 2; ks++) {
            const int c = ks * 16;
            uint32_t ah[4][4], al[4][4], bh[2][4], bl[2][4];
            #pragma unroll
            for (int mt = 0; mt < 4; mt++) {
                int r = wm * 64 + mt * 16 + ar;
                ldsm4(ah[mt], s2u(Ash + r * LDSS + c + ac));
                ldsm4(al[mt], s2u(Asl + r * LDSS + c + ac));
            }
            #pragma unroll
            for (int np = 0; np < 2; np++) {
                int n = wn * 32 + np * 16 + br;
                ldsm4(bh[np], s2u(Bsh + n * LDSS + c + bc));
                ldsm4(bl[np], s2u(Bsl + n * LDSS + c + bc));
            }
            #pragma unroll
            for (int mt = 0; mt < 4; mt++)
                #pragma unroll
                for (int nt = 0; nt < 4; nt++) {
                    const uint32_t* bph = &bh[nt >> 1][(nt & 1) * 2];
                    const uint32_t* bpl = &bl[nt >> 1][(nt & 1) * 2];
                    mma16816(acc[mt][nt], ah[mt], bph);
                    mma16816(acc[mt][nt], ah[mt], bpl);
                    mma16816(acc[mt][nt], al[mt], bph);
                }
        }
    };

    const int nit = K / 32;
    stage(0, 0);
    cpcommit();
    for (int it = 0; it < nit; it++) {
        if (it + 1 < nit) { stage((it + 1) & 1, (it + 1) * 32); cpcommit(); }
        if (it + 1 < nit) cpwait<1>(); else cpwait<0>();
        __syncthreads();
        compute(it & 1);
        __syncthreads();
    }

    #pragma unroll
    for (int mt = 0; mt < 4; mt++)
        #pragma unroll
        for (int nt = 0; nt < 4; nt++) {
            int r0 = row0 + wm * 64 + mt * 16 + (lane >> 2);
            int cc = col0 + wn * 32 + nt * 8 + ((lane & 3) << 1);
            float b0 = bias[cc], b1 = bias[cc + 1];
            #pragma unroll
            for (int half = 0; half < 2; half++) {
                int r = r0 + half * 8;
                float v0 = (acc[mt][nt][half * 2 + 0] + b0) * alpha;
                float v1 = (acc[mt][nt][half * 2 + 1] + b1) * alpha;
                uint32_t hi, lo;
                split2(v0, v1, hi, lo);
                *reinterpret_cast<uint32_t*>(&Ch[(size_t)r * ldc + cc]) = hi;
                *reinterpret_cast<uint32_t*>(&Cl[(size_t)r * ldc + cc]) = lo;
            }
        }
}

// ---------------------------------------------------------------------------
// O-projection GEMM (NT), fp16 2-term: out = ctx_fp16 @ (WoHi + WoLo)^T + bias.
// A single fp16 tile + B hi/lo -> 3 tiles/stage, 61440 B smem, 2 CTAs/SM.
// 2 MMAs per acc per ks (vs 3) -> 2/3 tensor work of proj_nt.
// ---------------------------------------------------------------------------
static constexpr int PROJ_O_SMEM = 2 * 3 * PTILE * (int)sizeof(__half);  // 61440

__global__ __launch_bounds__(256)
void proj_o(int K,
            const __half* __restrict__ A, int lda,
            const __half* __restrict__ Bth, const __half* __restrict__ Btl,
            float* __restrict__ Cf, int ldc, const float* __restrict__ bias)
{
    extern __shared__ __half smh[];   // [2][3][PTILE]

    const int tid = threadIdx.x, lane = tid & 31, wid = tid >> 5;
    const int wm = wid >> 2, wn = wid & 3;
    const int row0 = blockIdx.y * 128, col0 = blockIdx.x * 128;

    const __half* aP = A + (size_t)row0 * lda;
    const __half* bH = Bth + (size_t)col0 * K;
    const __half* bL = Btl + (size_t)col0 * K;

    const int g = lane >> 3, li = lane & 7;
    const int ar = ((g & 1) * 8) + li, ac = (g >> 1) * 8;
    const int br = ((g >> 1) * 8) + li, bc = (g & 1) * 8;

    float acc[4][4][4] = {};

    auto stage = [&](int st, int k0) {
        __half* d = smh + st * 3 * PTILE;
        #pragma unroll
        for (int i = tid; i < 512; i += 256) {
            int r = i >> 2, c = (i & 3) * 8;
            cpa16(s2u(d + 0 * PTILE + r * LDSS + c), aP + (size_t)r * lda + k0 + c);
            cpa16(s2u(d + 1 * PTILE + r * LDSS + c), bH + (size_t)r * K + k0 + c);
            cpa16(s2u(d + 2 * PTILE + r * LDSS + c), bL + (size_t)r * K + k0 + c);
        }
    };

    auto compute = [&](int st) {
        const __half* Ash = smh + st * 3 * PTILE;
        const __half* Bsh = Ash + PTILE;
        const __half* Bsl = Bsh + PTILE;
        #pragma unroll
        for (int ks = 0; ks < 2; ks++) {
            const int c = ks * 16;
            uint32_t ah[4][4], bh[2][4], bl[2][4];
            #pragma unroll
            for (int mt = 0; mt < 4; mt++) {
                int r = wm * 64 + mt * 16 + ar;
                ldsm4(ah[mt], s2u(Ash + r * LDSS + c + ac));
            }
            #pragma unroll
            for (int np = 0; np < 2; np++) {
                int n = wn * 32 + np * 16 + br;
                ldsm4(bh[np], s2u(Bsh + n * LDSS + c + bc));
                ldsm4(bl[np], s2u(Bsl + n * LDSS + c + bc));
            }
            #pragma unroll
            for (int mt = 0; mt < 4; mt++)
                #pragma unroll
                for (int nt = 0; nt < 4; nt++) {
                    const uint32_t* bph = &bh[nt >> 1][(nt & 1) * 2];
                    const uint32_t* bpl = &bl[nt >> 1][(nt & 1) * 2];
                    mma16816h(acc[mt][nt], ah[mt], bph);
                    mma16816h(acc[mt][nt], ah[mt], bpl);
                }
        }
    };

    const int nit = K / 32;
    stage(0, 0);
    cpcommit();
    for (int it = 0; it < nit; it++) {
        if (it + 1 < nit) { stage((it + 1) & 1, (it + 1) * 32); cpcommit(); }
        if (it + 1 < nit) cpwait<1>(); else cpwait<0>();
        __syncthreads();
        compute(it & 1);
        __syncthreads();
    }

    #pragma unroll
    for (int mt = 0; mt < 4; mt++)
        #pragma unroll
        for (int nt = 0; nt < 4; nt++) {
            int r0 = row0 + wm * 64 + mt * 16 + (lane >> 2);
            int cc = col0 + wn * 32 + nt * 8 + ((lane & 3) << 1);
            float b0 = bias[cc], b1 = bias[cc + 1];
            #pragma unroll
            for (int half = 0; half < 2; half++) {
                int r = r0 + half * 8;
                float2 o;
                o.x = acc[mt][nt][half * 2 + 0] + b0;
                o.y = acc[mt][nt][half * 2 + 1] + b1;
                *reinterpret_cast<float2*>(&Cf[(size_t)r * ldc + cc]) = o;
            }
        }
}

// ---------------------------------------------------------------------------
// Fused flash attention (R13-winning config: s-tile 64, 2 stages, 2 CTAs/SM,
// exp2 softmax, 3-term split PV). Epilogue now writes ctx as single fp16.
// ---------------------------------------------------------------------------
static constexpr int STILE = 64;
static constexpr int LDK = 72;
static constexpr int LDV = 72;
static constexpr int KTILE = STILE * LDK;
static constexpr int VTILE = 64 * LDV;
static constexpr int FSTAGE = 2 * KTILE + 2 * VTILE;
static constexpr int FLASH_SMEM = 2 * FSTAGE * (int)sizeof(__nv_bfloat16);  // 73728

__global__ __launch_bounds__(256, 2)
void flash_attn(const __nv_bfloat16* __restrict__ Qh, const __nv_bfloat16* __restrict__ Ql,
                const __nv_bfloat16* __restrict__ Kh, const __nv_bfloat16* __restrict__ Kl,
                const __nv_bfloat16* __restrict__ Vth, const __nv_bfloat16* __restrict__ Vtl,
                const float* __restrict__ mask, const float* __restrict__ head_mask,
                __half* __restrict__ Cf16)
{
    extern __shared__ __nv_bfloat16 smf[];   // [2][FSTAGE]

    const int tid = threadIdx.x, lane = tid & 31, wid = tid >> 5;
    const int z = blockIdx.y, bb = z >> 4, hh = z & 15;
    const int row0 = blockIdx.x * 128;
    const int tr = row0 + wid * 16 + (lane >> 2);

    const int g = lane >> 3, li = lane & 7;
    const int br = ((g >> 1) * 8) + li, bc = (g & 1) * 8;

    // ---- Q fragments (register-resident), k = 0..63; already log2e-scaled ----
    uint32_t qfh[4][4], qfl[4][4];
    {
        const size_t qrow = (size_t)(bb * T + tr) * EMB + hh * D;
        #pragma unroll
        for (int ks = 0; ks < 4; ks++) {
            const int c = ks * 16 + (lane & 3) * 2;
            qfh[ks][0] = ld32(Qh + qrow + c);
            qfh[ks][1] = ld32(Qh + qrow + (size_t)8 * EMB + c);
            qfh[ks][2] = ld32(Qh + qrow + c + 8);
            qfh[ks][3] = ld32(Qh + qrow + (size_t)8 * EMB + c + 8);
            qfl[ks][0] = ld32(Ql + qrow + c);
            qfl[ks][1] = ld32(Ql + qrow + (size_t)8 * EMB + c);
            qfl[ks][2] = ld32(Ql + qrow + c + 8);
            qfl[ks][3] = ld32(Ql + qrow + (size_t)8 * EMB + c + 8);
        }
    }

    float oacc[8][4] = {};
    float mrun[2] = {-1e30f, -1e30f};
    float lrun[2] = {0.0f, 0.0f};

    const __nv_bfloat16* kbase_h = Kh + (size_t)bb * S * EMB + hh * D;
    const __nv_bfloat16* kbase_l = Kl + (size_t)bb * S * EMB + hh * D;
    const __nv_bfloat16* vbase_h = Vth + (size_t)z * D * S;
    const __nv_bfloat16* vbase_l = Vtl + (size_t)z * D * S;
    const float* Mz = mask + (size_t)bb * T * S;

    auto stageKV = [&](int st, int s0) {
        __nv_bfloat16* kd  = smf + st * FSTAGE;
        __nv_bfloat16* kdl = kd + KTILE;
        __nv_bfloat16* vd  = kdl + KTILE;
        __nv_bfloat16* vdl = vd + VTILE;
        #pragma unroll
        for (int i = tid; i < 512; i += 256) {
            int r = i >> 3, c = (i & 7) * 8;
            cpa16(s2u(kd  + r * LDK + c), kbase_h + (size_t)(s0 + r) * EMB + c);
            cpa16(s2u(kdl + r * LDK + c), kbase_l + (size_t)(s0 + r) * EMB + c);
        }
        #pragma unroll
        for (int i = tid; i < 512; i += 256) {
            int r = i >> 3, c = (i & 7) * 8;
            cpa16(s2u(vd  + r * LDV + c), vbase_h + (size_t)r * S + s0 + c);
            cpa16(s2u(vdl + r * LDV + c), vbase_l + (size_t)r * S + s0 + c);
        }
    };

    stageKV(0, 0);
    cpcommit();

    constexpr int NS = S / STILE;   // 16
    for (int is = 0; is < NS; is++) {
        if (is + 1 < NS) { stageKV((is + 1) & 1, (is + 1) * STILE); cpcommit(); }
        if (is + 1 < NS) cpwait<1>(); else cpwait<0>();
        __syncthreads();

        const int s0 = is * STILE;
        const __nv_bfloat16* Ksh = smf + (is & 1) * FSTAGE;
        const __nv_bfloat16* Ksl = Ksh + KTILE;
        const __nv_bfloat16* Vsh = Ksl + KTILE;
        const __nv_bfloat16* Vsl = Vsh + VTILE;

        // ---- scores (log2 domain): 16(t) x 64(s) per warp ----
        float sacc[8][4] = {};
        #pragma unroll
        for (int ks = 0; ks < 4; ks++) {
            const int c = ks * 16;
            #pragma unroll
            for (int np = 0; np < 4; np++) {
                const int n = np * 16 + br;
                uint32_t kbh[4], kbl[4];
                ldsm4(kbh, s2u(Ksh + n * LDK + c + bc));
                ldsm4(kbl, s2u(Ksl + n * LDK + c + bc));
                mma16816(sacc[2 * np],     qfh[ks], kbh);
                mma16816(sacc[2 * np],     qfh[ks], kbl);
                mma16816(sacc[2 * np],     qfl[ks], kbh);
                mma16816(sacc[2 * np + 1], qfh[ks], kbh + 2);
                mma16816(sacc[2 * np + 1], qfh[ks], kbl + 2);
                mma16816(sacc[2 * np + 1], qfl[ks], kbh + 2);
            }
        }

        // ---- + mask * log2e (FFMA) ----
        #pragma unroll
        for (int nt = 0; nt < 8; nt++) {
            const int cg = s0 + nt * 8 + (lane & 3) * 2;
            float2 m0 = *reinterpret_cast<const float2*>(&Mz[(size_t)tr * S + cg]);
            float2 m1 = *reinterpret_cast<const float2*>(&Mz[(size_t)(tr + 8) * S + cg]);
            sacc[nt][0] = fmaf(m0.x, LOG2E, sacc[nt][0]);
            sacc[nt][1] = fmaf(m0.y, LOG2E, sacc[nt][1]);
            sacc[nt][2] = fmaf(m1.x, LOG2E, sacc[nt][2]);
            sacc[nt][3] = fmaf(m1.y, LOG2E, sacc[nt][3]);
        }

        // ---- online softmax in exp2 domain (per row-half) ----
        #pragma unroll
        for (int hf = 0; hf < 2; hf++) {
            float vm = -1e30f;
            #pragma unroll
            for (int nt = 0; nt < 8; nt++)
                vm = fmaxf(vm, fmaxf(sacc[nt][hf * 2], sacc[nt][hf * 2 + 1]));
            vm = fmaxf(vm, __shfl_xor_sync(0xffffffffu, vm, 1));
            vm = fmaxf(vm, __shfl_xor_sync(0xffffffffu, vm, 2));
            const float mnew = fmaxf(mrun[hf], vm);
            const float f = ex2(mrun[hf] - mnew);
            mrun[hf] = mnew;
            lrun[hf] *= f;
            #pragma unroll
            for (int nt = 0; nt < 8; nt++) {
                oacc[nt][hf * 2 + 0] *= f;
                oacc[nt][hf * 2 + 1] *= f;
            }
            float ls = 0.0f;
            #pragma unroll
            for (int nt = 0; nt < 8; nt++) {
                float e0 = ex2(sacc[nt][hf * 2 + 0] - mnew);
                float e1 = ex2(sacc[nt][hf * 2 + 1] - mnew);
                sacc[nt][hf * 2 + 0] = e0;
                sacc[nt][hf * 2 + 1] = e1;
                ls += e0 + e1;
            }
            lrun[hf] += ls;
        }

        // ---- PV: O(16t x 64d) += P(16t x 64s) @ Vt(64d x 64s)^T, 3-term ----
        #pragma unroll
        for (int ks = 0; ks < 4; ks++) {
            uint32_t ph[4], pl[4];
            split2(sacc[2 * ks][0],     sacc[2 * ks][1],     ph[0], pl[0]);
            split2(sacc[2 * ks][2],     sacc[2 * ks][3],     ph[1], pl[1]);
            split2(sacc[2 * ks + 1][0], sacc[2 * ks + 1][1], ph[2], pl[2]);
            split2(sacc[2 * ks + 1][2], sacc[2 * ks + 1][3], ph[3], pl[3]);
            const int c = ks * 16;
            #pragma unroll
            for (int np = 0; np < 4; np++) {
                const int n = np * 16 + br;
                uint32_t vbh[4], vbl[4];
                ldsm4(vbh, s2u(Vsh + n * LDV + c + bc));
                ldsm4(vbl, s2u(Vsl + n * LDV + c + bc));
                mma16816(oacc[2 * np],     ph, vbh);
                mma16816(oacc[2 * np],     ph, vbl);
                mma16816(oacc[2 * np],     pl, vbh);
                mma16816(oacc[2 * np + 1], ph, vbh + 2);
                mma16816(oacc[2 * np + 1], ph, vbl + 2);
                mma16816(oacc[2 * np + 1], pl, vbh + 2);
            }
        }
        __syncthreads();
    }

    // ---- epilogue: normalize, head-mask scale, write ctx as fp16 ----
    float scale[2];
    #pragma unroll
    for (int hf = 0; hf < 2; hf++) {
        float l = lrun[hf];
        l += __shfl_xor_sync(0xffffffffu, l, 1);
        l += __shfl_xor_sync(0xffffffffu, l, 2);
        scale[hf] = head_mask[hh] / l;
    }
    #pragma unroll
    for (int nt = 0; nt < 8; nt++) {
        const int cc = hh * D + nt * 8 + (lane & 3) * 2;
        #pragma unroll
        for (int hf = 0; hf < 2; hf++) {
            const size_t r = (size_t)(bb * T + tr + hf * 8);
            __half2 o = __floats2half2_rn(oacc[nt][hf * 2 + 0] * scale[hf],
                                          oacc[nt][hf * 2 + 1] * scale[hf]);
            *reinterpret_cast<__half2*>(&Cf16[r * EMB + cc]) = o;
        }
    }
}

// ---------------------------------------------------------------------------
extern "C" void kernel_launch(void* const* d_in, const int* in_sizes, int n_in,
                              void* d_out, int out_size)
{
    const float* hs   = (const float*)d_in[0];
    const float* kv   = (const float*)d_in[1];
    const float* mask = (const float*)d_in[2];
    const float* hm   = (const float*)d_in[3];
    const float* Wq   = (const float*)d_in[4];
    const float* bq   = (const float*)d_in[5];
    const float* Wk   = (const float*)d_in[6];
    const float* bk   = (const float*)d_in[7];
    const float* Wv   = (const float*)d_in[8];
    const float* bv   = (const float*)d_in[9];
    const float* Wo   = (const float*)d_in[10];
    const float* bo   = (const float*)d_in[11];
    float* out = (float*)d_out;

    __nv_bfloat16 *HSh, *HSl, *KVh, *KVl;
    __nv_bfloat16 *Qh, *Ql, *Kh, *Kl, *Vh, *Vl, *Vth, *Vtl;
    __nv_bfloat16 *Wqh, *Wql, *Wkh, *Wkl, *Wvh, *Wvl;
    __half *Cf16, *Wo16h, *Wo16l;
    cudaGetSymbolAddress((void**)&HSh, g_HShi); cudaGetSymbolAddress((void**)&HSl, g_HSlo);
    cudaGetSymbolAddress((void**)&KVh, g_KVhi); cudaGetSymbolAddress((void**)&KVl, g_KVlo);
    cudaGetSymbolAddress((void**)&Qh, g_Qhi);  cudaGetSymbolAddress((void**)&Ql, g_Qlo);
    cudaGetSymbolAddress((void**)&Kh, g_Khi);  cudaGetSymbolAddress((void**)&Kl, g_Klo);
    cudaGetSymbolAddress((void**)&Vh, g_Vhi);  cudaGetSymbolAddress((void**)&Vl, g_Vlo);
    cudaGetSymbolAddress((void**)&Vth, g_Vthi); cudaGetSymbolAddress((void**)&Vtl, g_Vtlo);
    cudaGetSymbolAddress((void**)&Cf16, g_Cf16);
    cudaGetSymbolAddress((void**)&Wqh, g_Wqthi); cudaGetSymbolAddress((void**)&Wql, g_Wqtlo);
    cudaGetSymbolAddress((void**)&Wkh, g_Wkthi); cudaGetSymbolAddress((void**)&Wkl, g_Wktlo);
    cudaGetSymbolAddress((void**)&Wvh, g_Wvthi); cudaGetSymbolAddress((void**)&Wvl, g_Wvtlo);
    cudaGetSymbolAddress((void**)&Wo16h, g_Wot16h); cudaGetSymbolAddress((void**)&Wo16l, g_Wot16l);

    cudaFuncSetAttribute(proj_nt, cudaFuncAttributeMaxDynamicSharedMemorySize, PROJ_SMEM);
    cudaFuncSetAttribute(proj_o,  cudaFuncAttributeMaxDynamicSharedMemorySize, PROJ_O_SMEM);
    cudaFuncSetAttribute(flash_attn, cudaFuncAttributeMaxDynamicSharedMemorySize, FLASH_SMEM);

    // Split activations fp32 -> bf16 hi/lo
    split_act<<<(B * T * QIN / 4 + 255) / 256, 256>>>(hs, HSh, HSl, B * T * QIN / 4);
    split_act<<<(B * S * KVIN / 4 + 255) / 256, 256>>>(kv, KVh, KVl, B * S * KVIN / 4);

    // Weight transpose + split (Wo in fp16 for the 2-term O-projection)
    wsplit_t<<<dim3(EMB / 32, QIN / 32), 256>>>(Wq, QIN, EMB, Wqh, Wql);
    wsplit_t<<<dim3(EMB / 32, KVIN / 32), 256>>>(Wk, KVIN, EMB, Wkh, Wkl);
    wsplit_t<<<dim3(EMB / 32, KVIN / 32), 256>>>(Wv, KVIN, EMB, Wvh, Wvl);
    wsplit_t16<<<dim3(EMB / 32, EMB / 32), 256>>>(Wo, EMB, EMB, Wo16h, Wo16l);

    // Projections -> split bf16 (Q pre-scaled by SCALING * log2e for exp2 softmax)
    proj_nt<<<dim3(EMB / 128, (B * T) / 128), 256, PROJ_SMEM>>>(
        QIN, HSh, HSl, QIN, Wqh, Wql, Qh, Ql, EMB, bq, SCALING * LOG2E);
    proj_nt<<<dim3(EMB / 128, (B * S) / 128), 256, PROJ_SMEM>>>(
        KVIN, KVh, KVl, KVIN, Wkh, Wkl, Kh, Kl, EMB, bk, 1.0f);
    proj_nt<<<dim3(EMB / 128, (B * S) / 128), 256, PROJ_SMEM>>>(
        KVIN, KVh, KVl, KVIN, Wvh, Wvl, Vh, Vl, EMB, bv, 1.0f);

    // V transpose per head
    vtrans<<<dim3(S / 64, 1, B * H), 256>>>(Vh, Vl, Vth, Vtl);

    // Fused scores + softmax + PV -> ctx fp16
    flash_attn<<<dim3(T / 128, B * H), 256, FLASH_SMEM>>>(
        Qh, Ql, Kh, Kl, Vth, Vtl, mask, hm, Cf16);

    // out = ctx @ Wo + bo  (fp16 2-term)
    proj_o<<<dim3(EMB / 128, (B * T) / 128), 256, PROJ_O_SMEM>>>(
        EMB, Cf16, EMB, Wo16h, Wo16l, out, EMB, bo);
}

// round 15
// speedup vs baseline: 1.6447x; 1.3105x over previous
#include <cuda_runtime.h>
#include <cuda_bf16.h>
#include <cuda_fp16.h>
#include <cstdint>

// Problem constants
static constexpr int B   = 8;
static constexpr int T   = 1024;
static constexpr int S   = 1024;
static constexpr int H   = 16;
static constexpr int D   = 64;
static constexpr int EMB = 1024;
static constexpr int QIN = 1024;
static constexpr int KVIN = 256;
static constexpr float SCALING = 0.125f;
static constexpr float LOG2E = 1.4426950408889634f;

// ---------------------------------------------------------------------------
// Scratch (__device__ globals; allocation-free rule). All fp16 now.
// ---------------------------------------------------------------------------
__device__ __half g_HS16[B * T * QIN];                   // hs rounded to fp16
__device__ __half g_KV16[B * S * KVIN];                  // kv rounded to fp16

__device__ __half g_Q16[B * T * EMB];                    // Q single fp16 (pre-scaled)
__device__ __half g_K16h[B * S * EMB], g_K16l[B * S * EMB];
__device__ __half g_V16h[B * S * EMB], g_V16l[B * S * EMB];
__device__ __half g_Vt16h[B * H * D * S], g_Vt16l[B * H * D * S];  // [z*D+d][S]
__device__ __half g_Cf16[B * T * EMB];                   // ctx fp16

__device__ __half g_Wq16h[EMB * QIN],  g_Wq16l[EMB * QIN];   // [N][K] fp16 hi/lo
__device__ __half g_Wk16h[EMB * KVIN], g_Wk16l[EMB * KVIN];
__device__ __half g_Wv16h[EMB * KVIN], g_Wv16l[EMB * KVIN];
__device__ __half g_Wo16h[EMB * EMB],  g_Wo16l[EMB * EMB];

// ---------------------------------------------------------------------------
// Low-level helpers
// ---------------------------------------------------------------------------
static constexpr int LDSS = 40;   // smem row stride (16-bit elems) for 32-col tiles

__device__ __forceinline__ uint32_t ld32h(const __half* p) {
    return *reinterpret_cast<const uint32_t*>(p);
}
__device__ __forceinline__ uint32_t s2u(const void* p) {
    return (uint32_t)__cvta_generic_to_shared(p);
}
__device__ __forceinline__ void cpa16(uint32_t dst, const void* src) {
    asm volatile("cp.async.cg.shared.global [%0], [%1], 16;\n" :: "r"(dst), "l"(src));
}
__device__ __forceinline__ void cpcommit() {
    asm volatile("cp.async.commit_group;\n");
}
template <int N> __device__ __forceinline__ void cpwait() {
    asm volatile("cp.async.wait_group %0;\n" :: "n"(N));
}
__device__ __forceinline__ void ldsm4(uint32_t* r, uint32_t a) {
    asm volatile("ldmatrix.sync.aligned.m8n8.x4.shared.b16 {%0,%1,%2,%3}, [%4];\n"
                 : "=r"(r[0]), "=r"(r[1]), "=r"(r[2]), "=r"(r[3]) : "r"(a));
}
__device__ __forceinline__ void mma16816h(float* c, const uint32_t* a, const uint32_t* b) {
    asm volatile(
        "mma.sync.aligned.m16n8k16.row.col.f32.f16.f16.f32 "
        "{%0,%1,%2,%3}, {%4,%5,%6,%7}, {%8,%9}, {%0,%1,%2,%3};\n"
        : "+f"(c[0]), "+f"(c[1]), "+f"(c[2]), "+f"(c[3])
        : "r"(a[0]), "r"(a[1]), "r"(a[2]), "r"(a[3]), "r"(b[0]), "r"(b[1]));
}
__device__ __forceinline__ float ex2(float x) {
    float y;
    asm("ex2.approx.f32 %0, %1;" : "=f"(y) : "f"(x));
    return y;
}
__device__ __forceinline__ uint32_t pack_h(float a, float b) {
    __half2 p = __floats2half2_rn(a, b);
    return *reinterpret_cast<uint32_t*>(&p);
}
__device__ __forceinline__ void split2h(float v0, float v1, uint32_t& hi, uint32_t& lo) {
    __half h0 = __float2half(v0), h1 = __float2half(v1);
    __half l0 = __float2half(v0 - __half2float(h0));
    __half l1 = __float2half(v1 - __half2float(h1));
    __half2 hp; hp.x = h0; hp.y = h1;
    __half2 lp; lp.x = l0; lp.y = l1;
    hi = *reinterpret_cast<uint32_t*>(&hp);
    lo = *reinterpret_cast<uint32_t*>(&lp);
}

// ---------------------------------------------------------------------------
// fp32 -> fp16 convert (elementwise, vectorized)
// ---------------------------------------------------------------------------
__global__ __launch_bounds__(256)
void conv16(const float* __restrict__ x, __half* __restrict__ y, int n4)
{
    int i = blockIdx.x * 256 + threadIdx.x;
    if (i >= n4) return;
    float4 v = reinterpret_cast<const float4*>(x)[i];
    __align__(8) __half h[4];
    h[0] = __float2half(v.x); h[1] = __float2half(v.y);
    h[2] = __float2half(v.z); h[3] = __float2half(v.w);
    reinterpret_cast<uint2*>(y)[i] = *reinterpret_cast<uint2*>(h);
}

// ---------------------------------------------------------------------------
// Weight transpose + split (fp16): W [K,N] fp32 -> Wt_hi/lo [N,K] fp16
// ---------------------------------------------------------------------------
__global__ __launch_bounds__(256)
void wsplit_t16(const float* __restrict__ W, int K, int N,
                __half* __restrict__ Whi, __half* __restrict__ Wlo)
{
    __shared__ float sm[32][33];
    const int k0 = blockIdx.y * 32, n0 = blockIdx.x * 32;
    const int tid = threadIdx.x;

    for (int i = tid; i < 32 * 8; i += 256) {
        int r = i >> 3, c4 = i & 7;
        float4 v = *reinterpret_cast<const float4*>(&W[(size_t)(k0 + r) * N + n0 + c4 * 4]);
        sm[r][c4 * 4 + 0] = v.x; sm[r][c4 * 4 + 1] = v.y;
        sm[r][c4 * 4 + 2] = v.z; sm[r][c4 * 4 + 3] = v.w;
    }
    __syncthreads();
    for (int i = tid; i < 32 * 8; i += 256) {
        int n = i >> 3, k4 = i & 7;
        __align__(8) __half h[4], l[4];
        #pragma unroll
        for (int j = 0; j < 4; j++) {
            float v = sm[k4 * 4 + j][n];
            h[j] = __float2half(v);
            l[j] = __float2half(v - __half2float(h[j]));
        }
        *reinterpret_cast<uint2*>(&Whi[(size_t)(n0 + n) * K + k0 + k4 * 4]) = *reinterpret_cast<uint2*>(h);
        *reinterpret_cast<uint2*>(&Wlo[(size_t)(n0 + n) * K + k0 + k4 * 4]) = *reinterpret_cast<uint2*>(l);
    }
}

// ---------------------------------------------------------------------------
// V transpose (fp16): V [b*S+s][h*D+d] -> Vt [(b*H+h)*D+d][s]
// ---------------------------------------------------------------------------
__global__ __launch_bounds__(256)
void vtrans16(const __half* __restrict__ Vh, const __half* __restrict__ Vl,
              __half* __restrict__ Vth, __half* __restrict__ Vtl)
{
    __shared__ __half sm[64][72];
    const int z = blockIdx.z, bb = z >> 4, hh = z & 15;
    const int s0 = blockIdx.x * 64;

    #pragma unroll
    for (int p = 0; p < 2; p++) {
        const __half* src = p ? Vl : Vh;
        __half* dst = p ? Vtl : Vth;
        const __half* sp = src + (size_t)(bb * S + s0) * EMB + hh * D;
        for (int i = threadIdx.x; i < 64 * 16; i += 256) {
            int s = i >> 4, d4 = i & 15;
            *reinterpret_cast<uint2*>(&sm[s][d4 * 4]) =
                *reinterpret_cast<const uint2*>(&sp[(size_t)s * EMB + d4 * 4]);
        }
        __syncthreads();
        __half* dp = dst + (size_t)z * D * S + s0;
        for (int i = threadIdx.x; i < 64 * 16; i += 256) {
            int d = i >> 4, s4 = i & 15;
            __align__(8) __half t[4];
            t[0] = sm[s4 * 4 + 0][d]; t[1] = sm[s4 * 4 + 1][d];
            t[2] = sm[s4 * 4 + 2][d]; t[3] = sm[s4 * 4 + 3][d];
            *reinterpret_cast<uint2*>(&dp[(size_t)d * S + s4 * 4]) = *reinterpret_cast<uint2*>(t);
        }
        __syncthreads();
    }
}

// ---------------------------------------------------------------------------
// fp16 2-term projection GEMM (NT): C = (A[M,K] @ (BtHi+BtLo)[N,K]^T + bias)*alpha
// A fp16 single; 3 tiles/stage (A, Bh, Bl) = 61440 B smem -> 2+ CTAs/SM.
// OUT: 0 = fp32 C, 1 = fp16 hi/lo pair, 2 = fp16 single.
// BM=BN=128, BK=32, 256 threads (8 warps 2x4), warp tile 64x32; 2 MMAs/acc/ks.
// ---------------------------------------------------------------------------
static constexpr int PTILE = 128 * LDSS;
static constexpr int PROJ16_SMEM = 2 * 3 * PTILE * (int)sizeof(__half);  // 61440

template <int OUT>
__global__ __launch_bounds__(256)
void proj16(int K,
            const __half* __restrict__ A, int lda,
            const __half* __restrict__ Bth, const __half* __restrict__ Btl,
            float* __restrict__ Cf, __half* __restrict__ Ch, __half* __restrict__ Cl,
            int ldc, const float* __restrict__ bias, float alpha)
{
    extern __shared__ __half smh[];   // [2][3][PTILE]

    const int tid = threadIdx.x, lane = tid & 31, wid = tid >> 5;
    const int wm = wid >> 2, wn = wid & 3;
    const int row0 = blockIdx.y * 128, col0 = blockIdx.x * 128;

    const __half* aP = A + (size_t)row0 * lda;
    const __half* bH = Bth + (size_t)col0 * K;
    const __half* bL = Btl + (size_t)col0 * K;

    const int g = lane >> 3, li = lane & 7;
    const int ar = ((g & 1) * 8) + li, ac = (g >> 1) * 8;
    const int br = ((g >> 1) * 8) + li, bc = (g & 1) * 8;

    float acc[4][4][4] = {};

    auto stage = [&](int st, int k0) {
        __half* d = smh + st * 3 * PTILE;
        #pragma unroll
        for (int i = tid; i < 512; i += 256) {
            int r = i >> 2, c = (i & 3) * 8;
            cpa16(s2u(d + 0 * PTILE + r * LDSS + c), aP + (size_t)r * lda + k0 + c);
            cpa16(s2u(d + 1 * PTILE + r * LDSS + c), bH + (size_t)r * K + k0 + c);
            cpa16(s2u(d + 2 * PTILE + r * LDSS + c), bL + (size_t)r * K + k0 + c);
        }
    };

    auto compute = [&](int st) {
        const __half* Ash = smh + st * 3 * PTILE;
        const __half* Bsh = Ash + PTILE;
        const __half* Bsl = Bsh + PTILE;
        #pragma unroll
        for (int ks = 0; ks < 2; ks++) {
            const int c = ks * 16;
            uint32_t ah[4][4], bh[2][4], bl[2][4];
            #pragma unroll
            for (int mt = 0; mt < 4; mt++) {
                int r = wm * 64 + mt * 16 + ar;
                ldsm4(ah[mt], s2u(Ash + r * LDSS + c + ac));
            }
            #pragma unroll
            for (int np = 0; np < 2; np++) {
                int n = wn * 32 + np * 16 + br;
                ldsm4(bh[np], s2u(Bsh + n * LDSS + c + bc));
                ldsm4(bl[np], s2u(Bsl + n * LDSS + c + bc));
            }
            #pragma unroll
            for (int mt = 0; mt < 4; mt++)
                #pragma unroll
                for (int nt = 0; nt < 4; nt++) {
                    const uint32_t* bph = &bh[nt >> 1][(nt & 1) * 2];
                    const uint32_t* bpl = &bl[nt >> 1][(nt & 1) * 2];
                    mma16816h(acc[mt][nt], ah[mt], bph);
                    mma16816h(acc[mt][nt], ah[mt], bpl);
                }
        }
    };

    const int nit = K / 32;
    stage(0, 0);
    cpcommit();
    for (int it = 0; it < nit; it++) {
        if (it + 1 < nit) { stage((it + 1) & 1, (it + 1) * 32); cpcommit(); }
        if (it + 1 < nit) cpwait<1>(); else cpwait<0>();
        __syncthreads();
        compute(it & 1);
        __syncthreads();
    }

    #pragma unroll
    for (int mt = 0; mt < 4; mt++)
        #pragma unroll
        for (int nt = 0; nt < 4; nt++) {
            int r0 = row0 + wm * 64 + mt * 16 + (lane >> 2);
            int cc = col0 + wn * 32 + nt * 8 + ((lane & 3) << 1);
            float b0 = bias[cc], b1 = bias[cc + 1];
            #pragma unroll
            for (int half = 0; half < 2; half++) {
                int r = r0 + half * 8;
                float v0 = (acc[mt][nt][half * 2 + 0] + b0) * alpha;
                float v1 = (acc[mt][nt][half * 2 + 1] + b1) * alpha;
                if (OUT == 0) {
                    float2 o; o.x = v0; o.y = v1;
                    *reinterpret_cast<float2*>(&Cf[(size_t)r * ldc + cc]) = o;
                } else if (OUT == 1) {
                    uint32_t hi, lo;
                    split2h(v0, v1, hi, lo);
                    *reinterpret_cast<uint32_t*>(&Ch[(size_t)r * ldc + cc]) = hi;
                    *reinterpret_cast<uint32_t*>(&Cl[(size_t)r * ldc + cc]) = lo;
                } else {
                    *reinterpret_cast<uint32_t*>(&Ch[(size_t)r * ldc + cc]) = pack_h(v0, v1);
                }
            }
        }
}

// ---------------------------------------------------------------------------
// Fused flash attention, full fp16 2-term:
// scores = Qf16 x (Khi + Klo),  PV = Pf16 x (Vhi + Vlo).
// R13-winning shape: s-tile 64, 2 stages, 2 CTAs/SM, exp2 softmax.
// ---------------------------------------------------------------------------
static constexpr int STILE = 64;
static constexpr int LDK = 72;
static constexpr int LDV = 72;
static constexpr int KTILE = STILE * LDK;
static constexpr int VTILE = 64 * LDV;
static constexpr int FSTAGE = 2 * KTILE + 2 * VTILE;
static constexpr int FLASH_SMEM = 2 * FSTAGE * (int)sizeof(__half);  // 73728

__global__ __launch_bounds__(256, 2)
void flash_attn(const __half* __restrict__ Q16,
                const __half* __restrict__ Kh, const __half* __restrict__ Kl,
                const __half* __restrict__ Vth, const __half* __restrict__ Vtl,
                const float* __restrict__ mask, const float* __restrict__ head_mask,
                __half* __restrict__ Cf16)
{
    extern __shared__ __half smf[];   // [2][FSTAGE]

    const int tid = threadIdx.x, lane = tid & 31, wid = tid >> 5;
    const int z = blockIdx.y, bb = z >> 4, hh = z & 15;
    const int row0 = blockIdx.x * 128;
    const int tr = row0 + wid * 16 + (lane >> 2);

    const int g = lane >> 3, li = lane & 7;
    const int br = ((g >> 1) * 8) + li, bc = (g & 1) * 8;

    // ---- Q fragments (single fp16, register-resident), k = 0..63 ----
    uint32_t qf[4][4];
    {
        const size_t qrow = (size_t)(bb * T + tr) * EMB + hh * D;
        #pragma unroll
        for (int ks = 0; ks < 4; ks++) {
            const int c = ks * 16 + (lane & 3) * 2;
            qf[ks][0] = ld32h(Q16 + qrow + c);
            qf[ks][1] = ld32h(Q16 + qrow + (size_t)8 * EMB + c);
            qf[ks][2] = ld32h(Q16 + qrow + c + 8);
            qf[ks][3] = ld32h(Q16 + qrow + (size_t)8 * EMB + c + 8);
        }
    }

    float oacc[8][4] = {};
    float mrun[2] = {-1e30f, -1e30f};
    float lrun[2] = {0.0f, 0.0f};

    const __half* kbase_h = Kh + (size_t)bb * S * EMB + hh * D;
    const __half* kbase_l = Kl + (size_t)bb * S * EMB + hh * D;
    const __half* vbase_h = Vth + (size_t)z * D * S;
    const __half* vbase_l = Vtl + (size_t)z * D * S;
    const float* Mz = mask + (size_t)bb * T * S;

    auto stageKV = [&](int st, int s0) {
        __half* kd  = smf + st * FSTAGE;
        __half* kdl = kd + KTILE;
        __half* vd  = kdl + KTILE;
        __half* vdl = vd + VTILE;
        #pragma unroll
        for (int i = tid; i < 512; i += 256) {
            int r = i >> 3, c = (i & 7) * 8;
            cpa16(s2u(kd  + r * LDK + c), kbase_h + (size_t)(s0 + r) * EMB + c);
            cpa16(s2u(kdl + r * LDK + c), kbase_l + (size_t)(s0 + r) * EMB + c);
        }
        #pragma unroll
        for (int i = tid; i < 512; i += 256) {
            int r = i >> 3, c = (i & 7) * 8;
            cpa16(s2u(vd  + r * LDV + c), vbase_h + (size_t)r * S + s0 + c);
            cpa16(s2u(vdl + r * LDV + c), vbase_l + (size_t)r * S + s0 + c);
        }
    };

    stageKV(0, 0);
    cpcommit();

    constexpr int NS = S / STILE;   // 16
    for (int is = 0; is < NS; is++) {
        if (is + 1 < NS) { stageKV((is + 1) & 1, (is + 1) * STILE); cpcommit(); }
        if (is + 1 < NS) cpwait<1>(); else cpwait<0>();
        __syncthreads();

        const int s0 = is * STILE;
        const __half* Ksh = smf + (is & 1) * FSTAGE;
        const __half* Ksl = Ksh + KTILE;
        const __half* Vsh = Ksl + KTILE;
        const __half* Vsl = Vsh + VTILE;

        // ---- scores (log2 domain): 16(t) x 64(s) per warp, 2-term ----
        float sacc[8][4] = {};
        #pragma unroll
        for (int ks = 0; ks < 4; ks++) {
            const int c = ks * 16;
            #pragma unroll
            for (int np = 0; np < 4; np++) {
                const int n = np * 16 + br;
                uint32_t kbh[4], kbl[4];
                ldsm4(kbh, s2u(Ksh + n * LDK + c + bc));
                ldsm4(kbl, s2u(Ksl + n * LDK + c + bc));
                mma16816h(sacc[2 * np],     qf[ks], kbh);
                mma16816h(sacc[2 * np],     qf[ks], kbl);
                mma16816h(sacc[2 * np + 1], qf[ks], kbh + 2);
                mma16816h(sacc[2 * np + 1], qf[ks], kbl + 2);
            }
        }

        // ---- + mask * log2e (FFMA) ----
        #pragma unroll
        for (int nt = 0; nt < 8; nt++) {
            const int cg = s0 + nt * 8 + (lane & 3) * 2;
            float2 m0 = *reinterpret_cast<const float2*>(&Mz[(size_t)tr * S + cg]);
            float2 m1 = *reinterpret_cast<const float2*>(&Mz[(size_t)(tr + 8) * S + cg]);
            sacc[nt][0] = fmaf(m0.x, LOG2E, sacc[nt][0]);
            sacc[nt][1] = fmaf(m0.y, LOG2E, sacc[nt][1]);
            sacc[nt][2] = fmaf(m1.x, LOG2E, sacc[nt][2]);
            sacc[nt][3] = fmaf(m1.y, LOG2E, sacc[nt][3]);
        }

        // ---- online softmax in exp2 domain (per row-half) ----
        #pragma unroll
        for (int hf = 0; hf < 2; hf++) {
            float vm = -1e30f;
            #pragma unroll
            for (int nt = 0; nt < 8; nt++)
                vm = fmaxf(vm, fmaxf(sacc[nt][hf * 2], sacc[nt][hf * 2 + 1]));
            vm = fmaxf(vm, __shfl_xor_sync(0xffffffffu, vm, 1));
            vm = fmaxf(vm, __shfl_xor_sync(0xffffffffu, vm, 2));
            const float mnew = fmaxf(mrun[hf], vm);
            const float f = ex2(mrun[hf] - mnew);
            mrun[hf] = mnew;
            lrun[hf] *= f;
            #pragma unroll
            for (int nt = 0; nt < 8; nt++) {
                oacc[nt][hf * 2 + 0] *= f;
                oacc[nt][hf * 2 + 1] *= f;
            }
            float ls = 0.0f;
            #pragma unroll
            for (int nt = 0; nt < 8; nt++) {
                float e0 = ex2(sacc[nt][hf * 2 + 0] - mnew);
                float e1 = ex2(sacc[nt][hf * 2 + 1] - mnew);
                sacc[nt][hf * 2 + 0] = e0;
                sacc[nt][hf * 2 + 1] = e1;
                ls += e0 + e1;
            }
            lrun[hf] += ls;
        }

        // ---- PV: O += P_f16 @ (Vhi + Vlo)^T, 2-term ----
        #pragma unroll
        for (int ks = 0; ks < 4; ks++) {
            uint32_t ph[4];
            ph[0] = pack_h(sacc[2 * ks][0],     sacc[2 * ks][1]);
            ph[1] = pack_h(sacc[2 * ks][2],     sacc[2 * ks][3]);
            ph[2] = pack_h(sacc[2 * ks + 1][0], sacc[2 * ks + 1][1]);
            ph[3] = pack_h(sacc[2 * ks + 1][2], sacc[2 * ks + 1][3]);
            const int c = ks * 16;
            #pragma unroll
            for (int np = 0; np < 4; np++) {
                const int n = np * 16 + br;
                uint32_t vbh[4], vbl[4];
                ldsm4(vbh, s2u(Vsh + n * LDV + c + bc));
                ldsm4(vbl, s2u(Vsl + n * LDV + c + bc));
                mma16816h(oacc[2 * np],     ph, vbh);
                mma16816h(oacc[2 * np],     ph, vbl);
                mma16816h(oacc[2 * np + 1], ph, vbh + 2);
                mma16816h(oacc[2 * np + 1], ph, vbl + 2);
            }
        }
        __syncthreads();
    }

    // ---- epilogue: normalize, head-mask scale, write ctx as fp16 ----
    float scale[2];
    #pragma unroll
    for (int hf = 0; hf < 2; hf++) {
        float l = lrun[hf];
        l += __shfl_xor_sync(0xffffffffu, l, 1);
        l += __shfl_xor_sync(0xffffffffu, l, 2);
        scale[hf] = head_mask[hh] / l;
    }
    #pragma unroll
    for (int nt = 0; nt < 8; nt++) {
        const int cc = hh * D + nt * 8 + (lane & 3) * 2;
        #pragma unroll
        for (int hf = 0; hf < 2; hf++) {
            const size_t r = (size_t)(bb * T + tr + hf * 8);
            __half2 o = __floats2half2_rn(oacc[nt][hf * 2 + 0] * scale[hf],
                                          oacc[nt][hf * 2 + 1] * scale[hf]);
            *reinterpret_cast<__half2*>(&Cf16[r * EMB + cc]) = o;
        }
    }
}

// ---------------------------------------------------------------------------
extern "C" void kernel_launch(void* const* d_in, const int* in_sizes, int n_in,
                              void* d_out, int out_size)
{
    const float* hs   = (const float*)d_in[0];
    const float* kv   = (const float*)d_in[1];
    const float* mask = (const float*)d_in[2];
    const float* hm   = (const float*)d_in[3];
    const float* Wq   = (const float*)d_in[4];
    const float* bq   = (const float*)d_in[5];
    const float* Wk   = (const float*)d_in[6];
    const float* bk   = (const float*)d_in[7];
    const float* Wv   = (const float*)d_in[8];
    const float* bv   = (const float*)d_in[9];
    const float* Wo   = (const float*)d_in[10];
    const float* bo   = (const float*)d_in[11];
    float* out = (float*)d_out;

    __half *HS16, *KV16, *Q16, *K16h, *K16l, *V16h, *V16l, *Vt16h, *Vt16l, *Cf16;
    __half *Wq16h, *Wq16l, *Wk16h, *Wk16l, *Wv16h, *Wv16l, *Wo16h, *Wo16l;
    cudaGetSymbolAddress((void**)&HS16, g_HS16);
    cudaGetSymbolAddress((void**)&KV16, g_KV16);
    cudaGetSymbolAddress((void**)&Q16, g_Q16);
    cudaGetSymbolAddress((void**)&K16h, g_K16h); cudaGetSymbolAddress((void**)&K16l, g_K16l);
    cudaGetSymbolAddress((void**)&V16h, g_V16h); cudaGetSymbolAddress((void**)&V16l, g_V16l);
    cudaGetSymbolAddress((void**)&Vt16h, g_Vt16h); cudaGetSymbolAddress((void**)&Vt16l, g_Vt16l);
    cudaGetSymbolAddress((void**)&Cf16, g_Cf16);
    cudaGetSymbolAddress((void**)&Wq16h, g_Wq16h); cudaGetSymbolAddress((void**)&Wq16l, g_Wq16l);
    cudaGetSymbolAddress((void**)&Wk16h, g_Wk16h); cudaGetSymbolAddress((void**)&Wk16l, g_Wk16l);
    cudaGetSymbolAddress((void**)&Wv16h, g_Wv16h); cudaGetSymbolAddress((void**)&Wv16l, g_Wv16l);
    cudaGetSymbolAddress((void**)&Wo16h, g_Wo16h); cudaGetSymbolAddress((void**)&Wo16l, g_Wo16l);

    cudaFuncSetAttribute(proj16<0>, cudaFuncAttributeMaxDynamicSharedMemorySize, PROJ16_SMEM);
    cudaFuncSetAttribute(proj16<1>, cudaFuncAttributeMaxDynamicSharedMemorySize, PROJ16_SMEM);
    cudaFuncSetAttribute(proj16<2>, cudaFuncAttributeMaxDynamicSharedMemorySize, PROJ16_SMEM);
    cudaFuncSetAttribute(flash_attn, cudaFuncAttributeMaxDynamicSharedMemorySize, FLASH_SMEM);

    // Round activations to fp16
    conv16<<<(B * T * QIN / 4 + 255) / 256, 256>>>(hs, HS16, B * T * QIN / 4);
    conv16<<<(B * S * KVIN / 4 + 255) / 256, 256>>>(kv, KV16, B * S * KVIN / 4);

    // Weight transpose + fp16 hi/lo split
    wsplit_t16<<<dim3(EMB / 32, QIN / 32), 256>>>(Wq, QIN, EMB, Wq16h, Wq16l);
    wsplit_t16<<<dim3(EMB / 32, KVIN / 32), 256>>>(Wk, KVIN, EMB, Wk16h, Wk16l);
    wsplit_t16<<<dim3(EMB / 32, KVIN / 32), 256>>>(Wv, KVIN, EMB, Wv16h, Wv16l);
    wsplit_t16<<<dim3(EMB / 32, EMB / 32), 256>>>(Wo, EMB, EMB, Wo16h, Wo16l);

    // Projections (fp16 2-term). Q -> single fp16, pre-scaled for exp2 softmax.
    proj16<2><<<dim3(EMB / 128, (B * T) / 128), 256, PROJ16_SMEM>>>(
        QIN, HS16, QIN, Wq16h, Wq16l, nullptr, Q16, nullptr, EMB, bq, SCALING * LOG2E);
    proj16<1><<<dim3(EMB / 128, (B * S) / 128), 256, PROJ16_SMEM>>>(
        KVIN, KV16, KVIN, Wk16h, Wk16l, nullptr, K16h, K16l, EMB, bk, 1.0f);
    proj16<1><<<dim3(EMB / 128, (B * S) / 128), 256, PROJ16_SMEM>>>(
        KVIN, KV16, KVIN, Wv16h, Wv16l, nullptr, V16h, V16l, EMB, bv, 1.0f);

    // V transpose per head
    vtrans16<<<dim3(S / 64, 1, B * H), 256>>>(V16h, V16l, Vt16h, Vt16l);

    // Fused scores + softmax + PV -> ctx fp16
    flash_attn<<<dim3(T / 128, B * H), 256, FLASH_SMEM>>>(
        Q16, K16h, K16l, Vt16h, Vt16l, mask, hm, Cf16);

    // out = ctx @ Wo + bo  (fp16 2-term, fp32 out)
    proj16<0><<<dim3(EMB / 128, (B * T) / 128), 256, PROJ16_SMEM>>>(
        EMB, Cf16, EMB, Wo16h, Wo16l, out, nullptr, nullptr, EMB, bo, 1.0f);
}